// round 10
// baseline (speedup 1.0000x reference)
#include <cuda_runtime.h>
#include <math.h>

#define BB 32
#define TT 2048
#define DF 128
#define NN 16
#define DY 8
#define RECSZ 256
#define NTOK 32
#define NCHUNK 64                 // TT / NTOK
#define LOG2PI 1.8378770664093455f

__device__ float g_rec[(size_t)BB * TT * RECSZ];   // zero-init; pad [192,256) never written
__device__ float g_llsum[BB];
__device__ int   g_flag[BB * NCHUNK];              // memset to 0 each launch

typedef unsigned long long ull;

__device__ __forceinline__ ull pk2(float a, float b) {
    ull r; asm("mov.b64 %0, {%1,%2};" : "=l"(r) : "f"(a), "f"(b)); return r;
}
__device__ __forceinline__ float sum2(ull v) {
    float a, b; asm("mov.b64 {%0,%1}, %2;" : "=f"(a), "=f"(b) : "l"(v)); return a + b;
}
__device__ __forceinline__ ull ffma2(ull a, ull b, ull c) {
    ull d; asm("fma.rn.f32x2 %0, %1, %2, %3;" : "=l"(d) : "l"(a), "l"(b), "l"(c)); return d;
}
__device__ __forceinline__ ull fadd2(ull a, ull b) {
    ull d; asm("add.rn.f32x2 %0, %1, %2;" : "=l"(d) : "l"(a), "l"(b)); return d;
}
__device__ __forceinline__ float frcp(float x) {
    float r; asm("rcp.approx.f32 %0, %1;" : "=f"(r) : "f"(x)); return r;
}
__device__ __forceinline__ void cp16(float* s, const void* g) {
    unsigned a = (unsigned)__cvta_generic_to_shared(s);
    asm volatile("cp.async.cg.shared.global [%0], [%1], 16;" :: "r"(a), "l"(g));
}
__device__ __forceinline__ void cpcommit() { asm volatile("cp.async.commit_group;"); }
template<int N> __device__ __forceinline__ void cpwait() {
    asm volatile("cp.async.wait_group %0;" :: "n"(N));
}

__device__ __forceinline__ float sp(float x) {
    return fmaxf(x, 0.f) + log1pf(expf(-fabsf(x)));
}
__device__ __forceinline__ float phik(float z, float k) {
    float kz = k * z;
    if (fabsf(kz) < 1e-4f) return 1.f + 0.5f * kz;
    return expm1f(kz) / kz;
}

__device__ __forceinline__ ull dot64(const float* __restrict__ row, const ull* xr2) {
    ull a0 = 0, a1 = 0, a2 = 0, a3 = 0;
#pragma unroll
    for (int k = 0; k < 8; k++) {
        ulonglong2 w0 = *(const ulonglong2*)(row + 8 * k);
        ulonglong2 w1 = *(const ulonglong2*)(row + 8 * k + 4);
        a0 = ffma2(w0.x, xr2[4 * k + 0], a0);
        a1 = ffma2(w0.y, xr2[4 * k + 1], a1);
        a2 = ffma2(w1.x, xr2[4 * k + 2], a2);
        a3 = ffma2(w1.y, xr2[4 * k + 3], a3);
    }
    return fadd2(fadd2(a0, a2), fadd2(a1, a3));
}

// producer dynamic smem layout (float offsets)
#define SM_SX    0
#define SM_SPART 4224
#define SM_SSML  12416
#define SM_W0    14080
#define SM_W1    30464
#define SM_TOT   46848
#define SM_BYTES (SM_TOT * 4)

__device__ __forceinline__ void stageW512(const float* src, float* dst, int tid) {
    const float4* s4 = (const float4*)src;
#pragma unroll
    for (int i = 0; i < 8; i++) {
        int idx = tid + i * 512;
        cp16(dst + idx * 4, s4 + idx);
    }
}

// ---------------------------------------------------------------------------
// Fused kernel: blocks 0..31 = scanners (1 warp), blocks 32.. = producers.
// ---------------------------------------------------------------------------
__global__ __launch_bounds__(512, 1) void fused_kernel(
    const float* __restrict__ x, const float* __restrict__ y,
    const float* __restrict__ a_raw,
    const float* __restrict__ Wg, const float* __restrict__ bg,
    const float* __restrict__ WB, const float* __restrict__ bB,
    const float* __restrict__ WC, const float* __restrict__ bC,
    const float* __restrict__ Ws, const float* __restrict__ bs,
    const float* __restrict__ WR, const float* __restrict__ bR,
    const float* __restrict__ p0, float* __restrict__ out)
{
    // ---- scanner static smem ----
    __shared__ __align__(16) float rec2[2][RECSZ];
    __shared__ __align__(16) float sP[320], sCP[160], sCPT[192];
    __shared__ __align__(16) float sS[72], se[8], hh[16], hp[16], yps[8], Sd[8];

    if (blockIdx.x >= BB) {
        // ================= PRODUCER =================
        extern __shared__ float dsm[];
        float* sx    = dsm + SM_SX;
        float* spart = dsm + SM_SPART;
        float* ssml  = dsm + SM_SSML;
        float* sW0   = dsm + SM_W0;
        float* sW1   = dsm + SM_W1;

        const int tid = threadIdx.x;
        const int warp = tid >> 5, l = tid & 31;
        const int wf = warp & 7, half = warp >> 3;
        const int co = half * 64;
        const int p = blockIdx.x - BB;
        const int batch = p & 31, tchunk = p >> 5;         // time-major order
        const size_t base = (size_t)batch * TT + (size_t)tchunk * NTOK;

        stageW512(WB, sW0, tid);
        cpcommit();

        for (int k = tid; k < NTOK * DF; k += 512) {
            int tok = k >> 7, g = k & 127;
            sx[tok * 132 + g] = x[(base + tok) * DF + g];
        }
        __syncthreads();

        ull xr2[32];
#pragma unroll
        for (int k = 0; k < 16; k++) {
            ulonglong2 v = *(const ulonglong2*)(sx + l * 132 + co + 4 * k);
            xr2[2 * k] = v.x; xr2[2 * k + 1] = v.y;
        }

#pragma unroll
        for (int rr = 0; rr < 4; rr++) {
            int r = wf + 8 * rr;
            if (r < 25) {
                const float* Wrow; float bias;
                if (r == 0)      { Wrow = Wg;                 bias = bg[0]; }
                else if (r < 17) { Wrow = Ws + (r - 1) * DF;  bias = bs[r - 1]; }
                else             { Wrow = WR + (r - 17) * DF; bias = bR[r - 17]; }
                float v = sum2(dot64(Wrow + co, xr2));
                if (half == 0) v += bias;
                ssml[r * 66 + half * 33 + l] = v;
            }
        }

        for (int n = 0; n < NN; n++) {
            float* cur = (n & 1) ? sW1 : sW0;
            float* nxt = (n & 1) ? sW0 : sW1;
            __syncthreads();
            if (n < 15) { stageW512(WB + (size_t)(n + 1) * 16384, nxt, tid); cpcommit(); cpwait<1>(); }
            else        { cpwait<0>(); }
            __syncthreads();

            ull accn2 = 0;
            float bacc = 0.f;
#pragma unroll 4
            for (int fi = 0; fi < 16; fi++) {
                int f = wf + 8 * fi;
                ull rp = dot64(cur + f * 128 + co, xr2);
                float xf = sx[l * 132 + f];
                accn2 = ffma2(pk2(xf, xf), rp, accn2);
                if (half == 0) bacc += xf * bB[n * 128 + f];
            }
            spart[warp * 512 + n * 32 + l] = sum2(accn2) + bacc;
        }
        __syncthreads();

        stageW512(WC, sW0, tid);
        cpcommit();

        {
            int tok = tid & 31, n = tid >> 5;
            float hsum = 0.f;
#pragma unroll
            for (int w2 = 0; w2 < 16; w2++) hsum += spart[w2 * 512 + n * 32 + tok];
            float gate = ssml[tok] + ssml[33 + tok];
            float Delta = sp(gate) + 1e-6f;
            Delta = fminf(fmaxf(Delta, 1e-3f), 1.0f);
            float a = -(sp(a_raw[n]) + 1e-6f);
            float z = fminf(fmaxf(Delta * a, -20.f), 20.f);
            float ez  = expf(z);
            float gam = phik(z, 1.f);
            float rho = phik(z, 2.f);
            float sg = sp(ssml[(1 + n) * 66 + tok] + ssml[(1 + n) * 66 + 33 + tok]) + 1e-6f + 1e-3f;
            size_t rb = (base + tok) * RECSZ;
            g_rec[rb + n]      = ez;
            g_rec[rb + 16 + n] = gam * Delta * hsum;
            g_rec[rb + 32 + n] = sg * sg * rho * Delta;
            if (n < DY) {
                g_rec[rb + 176 + n] = sp(ssml[(17 + n) * 66 + tok] + ssml[(17 + n) * 66 + 33 + tok])
                                      + 1e-6f + 1e-4f;
                g_rec[rb + 184 + n] = y[(base + tok) * DY + n];
            }
        }
        cpwait<0>();
        __syncthreads();

#pragma unroll 4
        for (int jj = 0; jj < 16; jj++) {
            int j = wf * 16 + jj;
            spart[j * 64 + half * 32 + l] = sum2(dot64(sW0 + j * 128 + co, xr2));
        }
        __syncthreads();

        for (int idx = tid; idx < 1024; idx += 512) {
            int tok = idx & 31, j4 = (idx >> 5) * 4;
            float4 v;
            v.x = spart[(j4 + 0) * 64 + tok] + spart[(j4 + 0) * 64 + 32 + tok] + bC[j4 + 0];
            v.y = spart[(j4 + 1) * 64 + tok] + spart[(j4 + 1) * 64 + 32 + tok] + bC[j4 + 1];
            v.z = spart[(j4 + 2) * 64 + tok] + spart[(j4 + 2) * 64 + 32 + tok] + bC[j4 + 2];
            v.w = spart[(j4 + 3) * 64 + tok] + spart[(j4 + 3) * 64 + 32 + tok] + bC[j4 + 3];
            *(float4*)(&g_rec[(base + tok) * RECSZ + 48 + j4]) = v;
        }

        // publish chunk
        __threadfence();
        __syncthreads();
        if (tid == 0) atomicExch(&g_flag[batch * NCHUNK + tchunk], 1);
        return;
    }

    // ================= SCANNER (1 warp per batch) =================
    const int b = blockIdx.x, l = threadIdx.x;
    if (l >= 32) return;
    const unsigned FULL = 0xffffffffu;

    const int i2 = l >> 1, jb = (l & 1) * 8;
    const int d4 = l >> 2, j04 = (l & 3) * 4;

#pragma unroll
    for (int u = 0; u < 8; u++)
        sP[i2 * 20 + jb + u] = (i2 == jb + u) ? fabsf(p0[i2]) : 0.f;
    if (l < 16) hh[l] = 0.f;
    float ll_s = 0.f, ll_c = 0.f;                // lane 24

    // wait chunk 0, stage record 0 into buffer 0
    {
        volatile int* f = &g_flag[b * NCHUNK];
        while (*f == 0) __nanosleep(64);
    }
    __threadfence();
    const float* RB = g_rec + (size_t)b * TT * RECSZ;
    {
        float4 a0 = *(const float4*)(RB + l * 8);
        float4 a1 = *(const float4*)(RB + l * 8 + 4);
        *(float4*)(&rec2[0][l * 8])     = a0;
        *(float4*)(&rec2[0][l * 8 + 4]) = a1;
    }

    float* om = out;
    float* ov = out + (size_t)BB * TT * DY;

    for (int t = 0; t < TT; t++) {
        __syncwarp(FULL);           // rec buffer, sP, hh from prev iter visible
        const float* rec = rec2[t & 1];
        float* rnx = rec2[(t + 1) & 1];

        // prefetch next record (LDG issued early, STS at iter bottom)
        float4 pfa, pfb;
        {
            int tn = (t + 1 < TT) ? t + 1 : t;
            if (tn > t && (tn & 31) == 0) {
                volatile int* f = &g_flag[b * NCHUNK + (tn >> 5)];
                while (*f == 0) __nanosleep(64);
                __threadfence();
            }
            const float* nx = RB + (size_t)tn * RECSZ;
            pfa = *(const float4*)(nx + l * 8);
            pfb = *(const float4*)(nx + l * 8 + 4);
        }

        // ---- stage A: hp (lanes<16) + CP ----
        if (l < 16) hp[l] = rec[l] * hh[l] + rec[16 + l];
        {
            float4 ez0 = *(const float4*)&rec[0];
            float4 ez1 = *(const float4*)&rec[4];
            float4 ez2 = *(const float4*)&rec[8];
            float4 ez3 = *(const float4*)&rec[12];
            float ezl[16] = {ez0.x,ez0.y,ez0.z,ez0.w, ez1.x,ez1.y,ez1.z,ez1.w,
                             ez2.x,ez2.y,ez2.z,ez2.w, ez3.x,ez3.y,ez3.z,ez3.w};
            const float* Crow = rec + 48 + d4 * 16;
            float4 ca = *(const float4*)(Crow);
            float4 cb = *(const float4*)(Crow + 4);
            float4 cc = *(const float4*)(Crow + 8);
            float4 cd = *(const float4*)(Crow + 12);
            float C[16] = {ca.x,ca.y,ca.z,ca.w, cb.x,cb.y,cb.z,cb.w,
                           cc.x,cc.y,cc.z,cc.w, cd.x,cd.y,cd.z,cd.w};
            float4 qv  = *(const float4*)&rec[32 + j04];
            float4 ezj = *(const float4*)&rec[j04];
            float aA0=0.f,aA1=0.f,aA2=0.f,aA3=0.f;
            float aB0=0.f,aB1=0.f,aB2=0.f,aB3=0.f;
#pragma unroll
            for (int n = 0; n < 16; n += 2) {
                float chA = C[n] * ezl[n];
                float chB = C[n + 1] * ezl[n + 1];
                float4 pA = *(const float4*)&sP[n * 20 + j04];
                float4 pB = *(const float4*)&sP[(n + 1) * 20 + j04];
                aA0 += chA * pA.x; aA1 += chA * pA.y; aA2 += chA * pA.z; aA3 += chA * pA.w;
                aB0 += chB * pB.x; aB1 += chB * pB.y; aB2 += chB * pB.z; aB3 += chB * pB.w;
            }
            float4 cp;
            cp.x = ezj.x * (aA0 + aB0) + C[j04 + 0] * qv.x;
            cp.y = ezj.y * (aA1 + aB1) + C[j04 + 1] * qv.y;
            cp.z = ezj.z * (aA2 + aB2) + C[j04 + 2] * qv.z;
            cp.w = ezj.w * (aA3 + aB3) + C[j04 + 3] * qv.w;
            *(float4*)&sCP[d4 * 20 + j04] = cp;
            sCPT[(j04 + 0) * 12 + d4] = cp.x;
            sCPT[(j04 + 1) * 12 + d4] = cp.y;
            sCPT[(j04 + 2) * 12 + d4] = cp.z;
            sCPT[(j04 + 3) * 12 + d4] = cp.w;
        }
        __syncwarp(FULL);

        // ---- stage B: S (2 per lane) + y_pred/e (lanes 24..31) ----
        {
            int d = d4, q0 = (l & 3) * 2;
            ulonglong2 g0 = *(const ulonglong2*)&sCP[d * 20];
            ulonglong2 g1 = *(const ulonglong2*)&sCP[d * 20 + 4];
            ulonglong2 g2 = *(const ulonglong2*)&sCP[d * 20 + 8];
            ulonglong2 g3 = *(const ulonglong2*)&sCP[d * 20 + 12];
#pragma unroll
            for (int qq = 0; qq < 2; qq++) {
                int q = q0 + qq;
                ulonglong2 c0 = *(const ulonglong2*)&rec[48 + q * 16];
                ulonglong2 c1 = *(const ulonglong2*)&rec[48 + q * 16 + 4];
                ulonglong2 c2 = *(const ulonglong2*)&rec[48 + q * 16 + 8];
                ulonglong2 c3 = *(const ulonglong2*)&rec[48 + q * 16 + 12];
                ull x0 = ffma2(g0.x, c0.x, ffma2(g0.y, c0.y, 0));
                ull x1 = ffma2(g1.x, c1.x, ffma2(g1.y, c1.y, 0));
                ull x2 = ffma2(g2.x, c2.x, ffma2(g2.y, c2.y, 0));
                ull x3 = ffma2(g3.x, c3.x, ffma2(g3.y, c3.y, 0));
                float s = sum2(fadd2(fadd2(x0, x1), fadd2(x2, x3)));
                if (d == q) { s += rec[176 + d]; Sd[d] = s; }
                sS[d * 9 + q] = s;
            }
            if (l >= 24) {
                int dd = l - 24;
                float yp = 0.f;
#pragma unroll
                for (int n = 0; n < 16; n++) yp += rec[48 + dd * 16 + n] * hp[n];
                yps[dd] = yp;
                se[dd] = rec[184 + dd] - yp;
            }
        }
        __syncwarp(FULL);

        // ---- stage C: 4x4 block Gauss-Jordan on [S | CP | e], lane = column ----
        float r[8];
        if (l < 8) {
#pragma unroll
            for (int d = 0; d < 8; d++) r[d] = sS[d * 9 + l];
        } else if (l < 24) {
            int m = l - 8;
#pragma unroll
            for (int d = 0; d < 8; d++) r[d] = sCP[d * 20 + m];
        } else if (l == 24) {
#pragma unroll
            for (int d = 0; d < 8; d++) r[d] = se[d];
        } else {
#pragma unroll
            for (int d = 0; d < 8; d++) r[d] = 0.f;
        }
        float pprod = 1.f;
#pragma unroll
        for (int k = 0; k < 2; k++) {
            const int kb = 4 * k;        // pivot block rows/cols kb..kb+3
            const int ob = 4 - kb;       // other block rows ob..ob+3
            // gather pivot block entries a[i][j] = A[kb+i][kb+j]
            float a00 = __shfl_sync(FULL, r[kb+0], kb+0), a01 = __shfl_sync(FULL, r[kb+0], kb+1);
            float a02 = __shfl_sync(FULL, r[kb+0], kb+2), a03 = __shfl_sync(FULL, r[kb+0], kb+3);
            float a10 = __shfl_sync(FULL, r[kb+1], kb+0), a11 = __shfl_sync(FULL, r[kb+1], kb+1);
            float a12 = __shfl_sync(FULL, r[kb+1], kb+2), a13 = __shfl_sync(FULL, r[kb+1], kb+3);
            float a20 = __shfl_sync(FULL, r[kb+2], kb+0), a21 = __shfl_sync(FULL, r[kb+2], kb+1);
            float a22 = __shfl_sync(FULL, r[kb+2], kb+2), a23 = __shfl_sync(FULL, r[kb+2], kb+3);
            float a30 = __shfl_sync(FULL, r[kb+3], kb+0), a31 = __shfl_sync(FULL, r[kb+3], kb+1);
            float a32 = __shfl_sync(FULL, r[kb+3], kb+2), a33 = __shfl_sync(FULL, r[kb+3], kb+3);
            // multipliers for elimination rows (independent of inverse -> overlaps)
            float w00 = __shfl_sync(FULL, r[ob+0], kb+0), w01 = __shfl_sync(FULL, r[ob+0], kb+1);
            float w02 = __shfl_sync(FULL, r[ob+0], kb+2), w03 = __shfl_sync(FULL, r[ob+0], kb+3);
            float w10 = __shfl_sync(FULL, r[ob+1], kb+0), w11 = __shfl_sync(FULL, r[ob+1], kb+1);
            float w12 = __shfl_sync(FULL, r[ob+1], kb+2), w13 = __shfl_sync(FULL, r[ob+1], kb+3);
            float w20 = __shfl_sync(FULL, r[ob+2], kb+0), w21 = __shfl_sync(FULL, r[ob+2], kb+1);
            float w22 = __shfl_sync(FULL, r[ob+2], kb+2), w23 = __shfl_sync(FULL, r[ob+2], kb+3);
            float w30 = __shfl_sync(FULL, r[ob+3], kb+0), w31 = __shfl_sync(FULL, r[ob+3], kb+1);
            float w32 = __shfl_sync(FULL, r[ob+3], kb+2), w33 = __shfl_sync(FULL, r[ob+3], kb+3);
            // 4x4 inverse via 2x2 Schur (per-lane, redundant)
            float dA = a00 * a11 - a01 * a10;
            float rA = frcp(dA);
            float iA00 =  a11 * rA, iA01 = -a01 * rA, iA10 = -a10 * rA, iA11 = a00 * rA;
            float e00 = a20 * iA00 + a21 * iA10, e01 = a20 * iA01 + a21 * iA11;
            float e10 = a30 * iA00 + a31 * iA10, e11 = a30 * iA01 + a31 * iA11;
            float s00 = a22 - (e00 * a02 + e01 * a12), s01 = a23 - (e00 * a03 + e01 * a13);
            float s10 = a32 - (e10 * a02 + e11 * a12), s11 = a33 - (e10 * a03 + e11 * a13);
            float dS = s00 * s11 - s01 * s10;
            float rS = frcp(dS);
            float iS00 =  s11 * rS, iS01 = -s01 * rS, iS10 = -s10 * rS, iS11 = s00 * rS;
            float f00 = iA00 * a02 + iA01 * a12, f01 = iA00 * a03 + iA01 * a13;
            float f10 = iA10 * a02 + iA11 * a12, f11 = iA10 * a03 + iA11 * a13;
            float m02 = -(f00 * iS00 + f01 * iS10), m03 = -(f00 * iS01 + f01 * iS11);
            float m12 = -(f10 * iS00 + f11 * iS10), m13 = -(f10 * iS01 + f11 * iS11);
            float m20 = -(iS00 * e00 + iS01 * e10), m21 = -(iS00 * e01 + iS01 * e11);
            float m30 = -(iS10 * e00 + iS11 * e10), m31 = -(iS10 * e01 + iS11 * e11);
            float m00 = iA00 - (m02 * e00 + m03 * e10), m01 = iA01 - (m02 * e01 + m03 * e11);
            float m10 = iA10 - (m12 * e00 + m13 * e10), m11 = iA11 - (m12 * e01 + m13 * e11);
            pprod *= dA * dS;
            // normalized pivot rows
            float rv0 = r[kb+0], rv1 = r[kb+1], rv2 = r[kb+2], rv3 = r[kb+3];
            float n0 = m00 * rv0 + m01 * rv1 + m02 * rv2 + m03 * rv3;
            float n1 = m10 * rv0 + m11 * rv1 + m12 * rv2 + m13 * rv3;
            float n2 = m20 * rv0 + m21 * rv1 + iS00 * rv2 + iS01 * rv3;
            float n3 = m30 * rv0 + m31 * rv1 + iS10 * rv2 + iS11 * rv3;
            // eliminate other-block rows
            r[ob+0] -= w00 * n0 + w01 * n1 + w02 * n2 + w03 * n3;
            r[ob+1] -= w10 * n0 + w11 * n1 + w12 * n2 + w13 * n3;
            r[ob+2] -= w20 * n0 + w21 * n1 + w22 * n2 + w23 * n3;
            r[ob+3] -= w30 * n0 + w31 * n1 + w32 * n2 + w33 * n3;
            r[kb+0] = n0; r[kb+1] = n1; r[kb+2] = n2; r[kb+3] = n3;
        }
        // lanes 8..23 now hold K'^T columns in r; lane 24 holds v.

        // ---- h_new directly on lanes 8..23 (no sKT round-trip) ----
        if (l >= 8 && l < 24) {
            int n = l - 8;
            ulonglong2 e0 = *(const ulonglong2*)&se[0];
            ulonglong2 e1 = *(const ulonglong2*)&se[4];
            ull acc = ffma2(pk2(r[0], r[1]), e0.x,
                      ffma2(pk2(r[2], r[3]), e0.y,
                      ffma2(pk2(r[4], r[5]), e1.x,
                      ffma2(pk2(r[6], r[7]), e1.y, 0))));
            hh[n] = hp[n] + sum2(acc);
        }
        if (l == 24) {
            float quad = 0.f;
#pragma unroll
            for (int d = 0; d < 8; d++) quad += se[d] * r[d];
            float ll = -0.5f * (logf(pprod) + quad + (float)DY * LOG2PI);
            float yk = ll - ll_c, tk = ll_s + yk;
            ll_c = (tk - ll_s) - yk; ll_s = tk;
        }

        // ---- P_new: K' column i2 fetched via shfl from lane 8+i2 ----
        {
            float m0 = __shfl_sync(FULL, r[0], 8 + i2);
            float m1 = __shfl_sync(FULL, r[1], 8 + i2);
            float m2 = __shfl_sync(FULL, r[2], 8 + i2);
            float m3 = __shfl_sync(FULL, r[3], 8 + i2);
            float m4 = __shfl_sync(FULL, r[4], 8 + i2);
            float m5 = __shfl_sync(FULL, r[5], 8 + i2);
            float m6 = __shfl_sync(FULL, r[6], 8 + i2);
            float m7 = __shfl_sync(FULL, r[7], 8 + i2);
            ull K0 = pk2(m0, m1), K1 = pk2(m2, m3);
            ull K2 = pk2(m4, m5), K3 = pk2(m6, m7);
            float ezi = rec[i2];
            float qi  = rec[32 + i2];
            float4 ej0 = *(const float4*)&rec[jb];
            float4 ej1 = *(const float4*)&rec[jb + 4];
            float ej[8] = {ej0.x,ej0.y,ej0.z,ej0.w, ej1.x,ej1.y,ej1.z,ej1.w};
            float4 pav = *(const float4*)&sP[i2 * 20 + jb];
            float4 pbv = *(const float4*)&sP[i2 * 20 + jb + 4];
            float pv[8] = {pav.x,pav.y,pav.z,pav.w, pbv.x,pbv.y,pbv.z,pbv.w};
            float o[8];
#pragma unroll
            for (int u = 0; u < 8; u++) {
                int j = jb + u;
                ulonglong2 c0 = *(const ulonglong2*)&sCPT[j * 12];
                ulonglong2 c1 = *(const ulonglong2*)&sCPT[j * 12 + 4];
                ull acc = ffma2(K0, c0.x, ffma2(K1, c0.y,
                          ffma2(K2, c1.x, ffma2(K3, c1.y, 0))));
                o[u] = ezi * ej[u] * pv[u] - sum2(acc) + ((i2 == j) ? qi : 0.f);
            }
            *(float4*)&sP[i2 * 20 + jb]     = make_float4(o[0], o[1], o[2], o[3]);
            *(float4*)&sP[i2 * 20 + jb + 4] = make_float4(o[4], o[5], o[6], o[7]);
        }
        if (l < DY) {
            size_t o = ((size_t)b * TT + t) * DY + l;
            om[o] = yps[l];
            ov[o] = Sd[l];
        }
        // stage next record into the other buffer (visible after loop-top sync)
        *(float4*)(&rnx[l * 8])     = pfa;
        *(float4*)(&rnx[l * 8 + 4]) = pfb;
    }
    if (l == 24) g_llsum[b] = ll_s;
}

__global__ void phase3_kernel(float* __restrict__ out) {
    float v = g_llsum[threadIdx.x];
#pragma unroll
    for (int o = 16; o > 0; o >>= 1) v += __shfl_down_sync(0xffffffffu, v, o);
    if (threadIdx.x == 0) {
        size_t off = (size_t)2 * BB * TT * DY;
        out[off]     = -v / (float)BB;
        out[off + 1] =  v / (float)(BB * TT);
    }
}

extern "C" void kernel_launch(void* const* d_in, const int* in_sizes, int n_in,
                              void* d_out, int out_size) {
    const float* x_feat = (const float*)d_in[0];
    const float* y      = (const float*)d_in[1];
    const float* a_raw  = (const float*)d_in[2];
    const float* W_gate = (const float*)d_in[3];
    const float* b_gate = (const float*)d_in[4];
    const float* W_B    = (const float*)d_in[5];
    const float* b_B    = (const float*)d_in[6];
    const float* W_C    = (const float*)d_in[7];
    const float* b_C    = (const float*)d_in[8];
    const float* W_sig  = (const float*)d_in[9];
    const float* b_sig  = (const float*)d_in[10];
    const float* W_R    = (const float*)d_in[11];
    const float* b_R    = (const float*)d_in[12];
    const float* p0     = (const float*)d_in[13];
    float* out = (float*)d_out;

    void* flag_ptr = nullptr;
    cudaGetSymbolAddress(&flag_ptr, g_flag);
    cudaMemsetAsync(flag_ptr, 0, BB * NCHUNK * sizeof(int), 0);

    cudaFuncSetAttribute(fused_kernel,
                         cudaFuncAttributeMaxDynamicSharedMemorySize, SM_BYTES);
    fused_kernel<<<BB + (BB * TT) / NTOK, 512, SM_BYTES>>>(
        x_feat, y, a_raw, W_gate, b_gate, W_B, b_B, W_C, b_C,
        W_sig, b_sig, W_R, b_R, p0, out);
    phase3_kernel<<<1, 32>>>(out);
}

// round 11
// speedup vs baseline: 1.1336x; 1.1336x over previous
#include <cuda_runtime.h>
#include <math.h>

#define BB 32
#define TT 2048
#define DF 128
#define NN 16
#define DY 8
#define RECSZ 256
#define NTOK 32
#define NCHUNK 64                 // TT / NTOK
#define LOG2PI 1.8378770664093455f
#define LN2F 0.6931471805599453f

__device__ float g_rec[(size_t)BB * TT * RECSZ];   // zero-init; pad [192,256) never written
__device__ float g_llsum[BB];
__device__ int   g_flag[BB * NCHUNK];              // memset to 0 each launch

typedef unsigned long long ull;

__device__ __forceinline__ ull pk2(float a, float b) {
    ull r; asm("mov.b64 %0, {%1,%2};" : "=l"(r) : "f"(a), "f"(b)); return r;
}
__device__ __forceinline__ float sum2(ull v) {
    float a, b; asm("mov.b64 {%0,%1}, %2;" : "=f"(a), "=f"(b) : "l"(v)); return a + b;
}
__device__ __forceinline__ ull ffma2(ull a, ull b, ull c) {
    ull d; asm("fma.rn.f32x2 %0, %1, %2, %3;" : "=l"(d) : "l"(a), "l"(b), "l"(c)); return d;
}
__device__ __forceinline__ ull fadd2(ull a, ull b) {
    ull d; asm("add.rn.f32x2 %0, %1, %2;" : "=l"(d) : "l"(a), "l"(b)); return d;
}
__device__ __forceinline__ float frcp(float x) {
    float r; asm("rcp.approx.f32 %0, %1;" : "=f"(r) : "f"(x)); return r;
}
__device__ __forceinline__ void cp16(float* s, const void* g) {
    unsigned a = (unsigned)__cvta_generic_to_shared(s);
    asm volatile("cp.async.cg.shared.global [%0], [%1], 16;" :: "r"(a), "l"(g));
}
__device__ __forceinline__ void cpcommit() { asm volatile("cp.async.commit_group;"); }
template<int N> __device__ __forceinline__ void cpwait() {
    asm volatile("cp.async.wait_group %0;" :: "n"(N));
}

__device__ __forceinline__ float sp(float x) {
    return fmaxf(x, 0.f) + log1pf(expf(-fabsf(x)));
}
__device__ __forceinline__ float phik(float z, float k) {
    float kz = k * z;
    if (fabsf(kz) < 1e-4f) return 1.f + 0.5f * kz;
    return expm1f(kz) / kz;
}

__device__ __forceinline__ ull dot64(const float* __restrict__ row, const ull* xr2) {
    ull a0 = 0, a1 = 0, a2 = 0, a3 = 0;
#pragma unroll
    for (int k = 0; k < 8; k++) {
        ulonglong2 w0 = *(const ulonglong2*)(row + 8 * k);
        ulonglong2 w1 = *(const ulonglong2*)(row + 8 * k + 4);
        a0 = ffma2(w0.x, xr2[4 * k + 0], a0);
        a1 = ffma2(w0.y, xr2[4 * k + 1], a1);
        a2 = ffma2(w1.x, xr2[4 * k + 2], a2);
        a3 = ffma2(w1.y, xr2[4 * k + 3], a3);
    }
    return fadd2(fadd2(a0, a2), fadd2(a1, a3));
}

// producer dynamic smem layout (float offsets)
#define SM_SX    0
#define SM_SPART 4224
#define SM_SSML  12416
#define SM_W0    14080
#define SM_W1    30464
#define SM_TOT   46848
#define SM_BYTES (SM_TOT * 4)

__device__ __forceinline__ void stageW512(const float* src, float* dst, int tid) {
    const float4* s4 = (const float4*)src;
#pragma unroll
    for (int i = 0; i < 8; i++) {
        int idx = tid + i * 512;
        cp16(dst + idx * 4, s4 + idx);
    }
}

// ---------------------------------------------------------------------------
// Fused kernel: blocks 0..31 = scanners (1 warp), blocks 32.. = producers.
// ---------------------------------------------------------------------------
__global__ __launch_bounds__(512, 1) void fused_kernel(
    const float* __restrict__ x, const float* __restrict__ y,
    const float* __restrict__ a_raw,
    const float* __restrict__ Wg, const float* __restrict__ bg,
    const float* __restrict__ WB, const float* __restrict__ bB,
    const float* __restrict__ WC, const float* __restrict__ bC,
    const float* __restrict__ Ws, const float* __restrict__ bs,
    const float* __restrict__ WR, const float* __restrict__ bR,
    const float* __restrict__ p0, float* __restrict__ out)
{
    // ---- scanner static smem ----
    __shared__ __align__(16) float rec2[2][RECSZ];
    __shared__ __align__(16) float sP[320], sCP[160], sCPT[192];
    __shared__ __align__(16) float sS[72], se[8], hh[16], hp[16];

    if (blockIdx.x >= BB) {
        // ================= PRODUCER =================
        extern __shared__ float dsm[];
        float* sx    = dsm + SM_SX;
        float* spart = dsm + SM_SPART;
        float* ssml  = dsm + SM_SSML;
        float* sW0   = dsm + SM_W0;
        float* sW1   = dsm + SM_W1;

        const int tid = threadIdx.x;
        const int warp = tid >> 5, l = tid & 31;
        const int wf = warp & 7, half = warp >> 3;
        const int co = half * 64;
        const int p = blockIdx.x - BB;
        const int batch = p & 31, tchunk = p >> 5;         // time-major order
        const size_t base = (size_t)batch * TT + (size_t)tchunk * NTOK;

        stageW512(WB, sW0, tid);
        cpcommit();

        for (int k = tid; k < NTOK * DF; k += 512) {
            int tok = k >> 7, g = k & 127;
            sx[tok * 132 + g] = x[(base + tok) * DF + g];
        }
        __syncthreads();

        ull xr2[32];
#pragma unroll
        for (int k = 0; k < 16; k++) {
            ulonglong2 v = *(const ulonglong2*)(sx + l * 132 + co + 4 * k);
            xr2[2 * k] = v.x; xr2[2 * k + 1] = v.y;
        }

#pragma unroll
        for (int rr = 0; rr < 4; rr++) {
            int r = wf + 8 * rr;
            if (r < 25) {
                const float* Wrow; float bias;
                if (r == 0)      { Wrow = Wg;                 bias = bg[0]; }
                else if (r < 17) { Wrow = Ws + (r - 1) * DF;  bias = bs[r - 1]; }
                else             { Wrow = WR + (r - 17) * DF; bias = bR[r - 17]; }
                float v = sum2(dot64(Wrow + co, xr2));
                if (half == 0) v += bias;
                ssml[r * 66 + half * 33 + l] = v;
            }
        }

        for (int n = 0; n < NN; n++) {
            float* cur = (n & 1) ? sW1 : sW0;
            float* nxt = (n & 1) ? sW0 : sW1;
            __syncthreads();
            if (n < 15) { stageW512(WB + (size_t)(n + 1) * 16384, nxt, tid); cpcommit(); cpwait<1>(); }
            else        { cpwait<0>(); }
            __syncthreads();

            ull accn2 = 0;
            float bacc = 0.f;
#pragma unroll 4
            for (int fi = 0; fi < 16; fi++) {
                int f = wf + 8 * fi;
                ull rp = dot64(cur + f * 128 + co, xr2);
                float xf = sx[l * 132 + f];
                accn2 = ffma2(pk2(xf, xf), rp, accn2);
                if (half == 0) bacc += xf * bB[n * 128 + f];
            }
            spart[warp * 512 + n * 32 + l] = sum2(accn2) + bacc;
        }
        __syncthreads();

        stageW512(WC, sW0, tid);
        cpcommit();

        {
            int tok = tid & 31, n = tid >> 5;
            float hsum = 0.f;
#pragma unroll
            for (int w2 = 0; w2 < 16; w2++) hsum += spart[w2 * 512 + n * 32 + tok];
            float gate = ssml[tok] + ssml[33 + tok];
            float Delta = sp(gate) + 1e-6f;
            Delta = fminf(fmaxf(Delta, 1e-3f), 1.0f);
            float a = -(sp(a_raw[n]) + 1e-6f);
            float z = fminf(fmaxf(Delta * a, -20.f), 20.f);
            float ez  = expf(z);
            float gam = phik(z, 1.f);
            float rho = phik(z, 2.f);
            float sg = sp(ssml[(1 + n) * 66 + tok] + ssml[(1 + n) * 66 + 33 + tok]) + 1e-6f + 1e-3f;
            size_t rb = (base + tok) * RECSZ;
            g_rec[rb + n]      = ez;
            g_rec[rb + 16 + n] = gam * Delta * hsum;
            g_rec[rb + 32 + n] = sg * sg * rho * Delta;
            if (n < DY) {
                g_rec[rb + 176 + n] = sp(ssml[(17 + n) * 66 + tok] + ssml[(17 + n) * 66 + 33 + tok])
                                      + 1e-6f + 1e-4f;
                g_rec[rb + 184 + n] = y[(base + tok) * DY + n];
            }
        }
        cpwait<0>();
        __syncthreads();

#pragma unroll 4
        for (int jj = 0; jj < 16; jj++) {
            int j = wf * 16 + jj;
            spart[j * 64 + half * 32 + l] = sum2(dot64(sW0 + j * 128 + co, xr2));
        }
        __syncthreads();

        for (int idx = tid; idx < 1024; idx += 512) {
            int tok = idx & 31, j4 = (idx >> 5) * 4;
            float4 v;
            v.x = spart[(j4 + 0) * 64 + tok] + spart[(j4 + 0) * 64 + 32 + tok] + bC[j4 + 0];
            v.y = spart[(j4 + 1) * 64 + tok] + spart[(j4 + 1) * 64 + 32 + tok] + bC[j4 + 1];
            v.z = spart[(j4 + 2) * 64 + tok] + spart[(j4 + 2) * 64 + 32 + tok] + bC[j4 + 2];
            v.w = spart[(j4 + 3) * 64 + tok] + spart[(j4 + 3) * 64 + 32 + tok] + bC[j4 + 3];
            *(float4*)(&g_rec[(base + tok) * RECSZ + 48 + j4]) = v;
        }

        // publish chunk
        __threadfence();
        __syncthreads();
        if (tid == 0) atomicExch(&g_flag[batch * NCHUNK + tchunk], 1);
        return;
    }

    // ================= SCANNER (1 warp per batch) =================
    const int b = blockIdx.x, l = threadIdx.x;
    if (l >= 32) return;
    const unsigned FULL = 0xffffffffu;

    const int i2 = l >> 1, jb = (l & 1) * 8;
    const int d4 = l >> 2, j04 = (l & 3) * 4;

#pragma unroll
    for (int u = 0; u < 8; u++)
        sP[i2 * 20 + jb + u] = (i2 == jb + u) ? fabsf(p0[i2]) : 0.f;
    if (l < 16) hh[l] = 0.f;
    // lane 24 accumulators: quad sum (Kahan) + logdet product (mant, exp)
    float q_s = 0.f, q_c = 0.f;
    float mant = 1.f; int eacc = 0;

    // wait chunk 0, stage record 0 into buffer 0
    {
        volatile int* f = &g_flag[b * NCHUNK];
        while (*f == 0) __nanosleep(64);
    }
    __threadfence();
    const float* RB = g_rec + (size_t)b * TT * RECSZ;
    {
        float4 a0 = *(const float4*)(RB + l * 8);
        float4 a1 = *(const float4*)(RB + l * 8 + 4);
        *(float4*)(&rec2[0][l * 8])     = a0;
        *(float4*)(&rec2[0][l * 8 + 4]) = a1;
    }

    float* om = out;
    float* ov = out + (size_t)BB * TT * DY;

    for (int t = 0; t < TT; t++) {
        __syncwarp(FULL);           // rec buffer, sP, hh from prev iter visible
        const float* rec = rec2[t & 1];
        float* rnx = rec2[(t + 1) & 1];

        // prefetch next record (LDG issued early, STS at iter bottom)
        float4 pfa, pfb;
        {
            int tn = (t + 1 < TT) ? t + 1 : t;
            if (tn > t && (tn & 31) == 0) {
                volatile int* f = &g_flag[b * NCHUNK + (tn >> 5)];
                while (*f == 0) __nanosleep(64);
                __threadfence();
            }
            const float* nx = RB + (size_t)tn * RECSZ;
            pfa = *(const float4*)(nx + l * 8);
            pfb = *(const float4*)(nx + l * 8 + 4);
        }

        // ---- stage A: hp (lanes<16) + CP ----
        if (l < 16) hp[l] = rec[l] * hh[l] + rec[16 + l];
        {
            float4 ez0 = *(const float4*)&rec[0];
            float4 ez1 = *(const float4*)&rec[4];
            float4 ez2 = *(const float4*)&rec[8];
            float4 ez3 = *(const float4*)&rec[12];
            float ezl[16] = {ez0.x,ez0.y,ez0.z,ez0.w, ez1.x,ez1.y,ez1.z,ez1.w,
                             ez2.x,ez2.y,ez2.z,ez2.w, ez3.x,ez3.y,ez3.z,ez3.w};
            const float* Crow = rec + 48 + d4 * 16;
            float4 ca = *(const float4*)(Crow);
            float4 cb = *(const float4*)(Crow + 4);
            float4 cc = *(const float4*)(Crow + 8);
            float4 cd = *(const float4*)(Crow + 12);
            float C[16] = {ca.x,ca.y,ca.z,ca.w, cb.x,cb.y,cb.z,cb.w,
                           cc.x,cc.y,cc.z,cc.w, cd.x,cd.y,cd.z,cd.w};
            float4 qv  = *(const float4*)&rec[32 + j04];
            float4 ezj = *(const float4*)&rec[j04];
            float aA0=0.f,aA1=0.f,aA2=0.f,aA3=0.f;
            float aB0=0.f,aB1=0.f,aB2=0.f,aB3=0.f;
#pragma unroll
            for (int n = 0; n < 16; n += 2) {
                float chA = C[n] * ezl[n];
                float chB = C[n + 1] * ezl[n + 1];
                float4 pA = *(const float4*)&sP[n * 20 + j04];
                float4 pB = *(const float4*)&sP[(n + 1) * 20 + j04];
                aA0 += chA * pA.x; aA1 += chA * pA.y; aA2 += chA * pA.z; aA3 += chA * pA.w;
                aB0 += chB * pB.x; aB1 += chB * pB.y; aB2 += chB * pB.z; aB3 += chB * pB.w;
            }
            float4 cp;
            cp.x = ezj.x * (aA0 + aB0) + C[j04 + 0] * qv.x;
            cp.y = ezj.y * (aA1 + aB1) + C[j04 + 1] * qv.y;
            cp.z = ezj.z * (aA2 + aB2) + C[j04 + 2] * qv.z;
            cp.w = ezj.w * (aA3 + aB3) + C[j04 + 3] * qv.w;
            *(float4*)&sCP[d4 * 20 + j04] = cp;
            sCPT[(j04 + 0) * 12 + d4] = cp.x;
            sCPT[(j04 + 1) * 12 + d4] = cp.y;
            sCPT[(j04 + 2) * 12 + d4] = cp.z;
            sCPT[(j04 + 3) * 12 + d4] = cp.w;
        }
        __syncwarp(FULL);

        // ---- stage B: S (2 per lane, diag -> ov direct) + y_pred/e (lanes 24..31) ----
        {
            int d = d4, q0 = (l & 3) * 2;
            ulonglong2 g0 = *(const ulonglong2*)&sCP[d * 20];
            ulonglong2 g1 = *(const ulonglong2*)&sCP[d * 20 + 4];
            ulonglong2 g2 = *(const ulonglong2*)&sCP[d * 20 + 8];
            ulonglong2 g3 = *(const ulonglong2*)&sCP[d * 20 + 12];
#pragma unroll
            for (int qq = 0; qq < 2; qq++) {
                int q = q0 + qq;
                ulonglong2 c0 = *(const ulonglong2*)&rec[48 + q * 16];
                ulonglong2 c1 = *(const ulonglong2*)&rec[48 + q * 16 + 4];
                ulonglong2 c2 = *(const ulonglong2*)&rec[48 + q * 16 + 8];
                ulonglong2 c3 = *(const ulonglong2*)&rec[48 + q * 16 + 12];
                ull x0 = ffma2(g0.x, c0.x, ffma2(g0.y, c0.y, 0));
                ull x1 = ffma2(g1.x, c1.x, ffma2(g1.y, c1.y, 0));
                ull x2 = ffma2(g2.x, c2.x, ffma2(g2.y, c2.y, 0));
                ull x3 = ffma2(g3.x, c3.x, ffma2(g3.y, c3.y, 0));
                float s = sum2(fadd2(fadd2(x0, x1), fadd2(x2, x3)));
                if (d == q) {
                    s += rec[176 + d];
                    ov[((size_t)b * TT + t) * DY + d] = s;   // S diag out, direct
                }
                sS[d * 9 + q] = s;
            }
            if (l >= 24) {
                int dd = l - 24;
                float yp = 0.f;
#pragma unroll
                for (int n = 0; n < 16; n++) yp += rec[48 + dd * 16 + n] * hp[n];
                om[((size_t)b * TT + t) * DY + dd] = yp;     // y_pred out, direct
                se[dd] = rec[184 + dd] - yp;
            }
        }
        __syncwarp(FULL);

        // ---- stage C: 2x2 block Gauss-Jordan on [S | CP | e], lane = column ----
        float r[8];
        if (l < 8) {
#pragma unroll
            for (int d = 0; d < 8; d++) r[d] = sS[d * 9 + l];
        } else if (l < 24) {
            int m = l - 8;
#pragma unroll
            for (int d = 0; d < 8; d++) r[d] = sCP[d * 20 + m];
        } else if (l == 24) {
#pragma unroll
            for (int d = 0; d < 8; d++) r[d] = se[d];
        } else {
#pragma unroll
            for (int d = 0; d < 8; d++) r[d] = 0.f;
        }
        float pprod = 1.f;
#pragma unroll
        for (int k = 0; k < 4; k++) {
            const int p0i = 2 * k, p1i = 2 * k + 1;
            float r0 = r[p0i], r1 = r[p1i];
            float pa = __shfl_sync(FULL, r0, p0i);   // A[p0][p0]
            float pc = __shfl_sync(FULL, r1, p0i);   // A[p1][p0]
            float pb = __shfl_sync(FULL, r0, p1i);   // A[p0][p1]
            float pd = __shfl_sync(FULL, r1, p1i);   // A[p1][p1]
            float det = pa * pd - pb * pc;
            pprod *= det;
            float rdet = frcp(det);
            float n0 = rdet * (pd * r0 - pb * r1);
            float n1 = rdet * (pa * r1 - pc * r0);
#pragma unroll
            for (int i = 0; i < 8; i++) {
                if (i == p0i || i == p1i) continue;
                float m0 = __shfl_sync(FULL, r[i], p0i);
                float m1 = __shfl_sync(FULL, r[i], p1i);
                r[i] -= m0 * n0 + m1 * n1;
            }
            r[p0i] = n0; r[p1i] = n1;
        }
        // lanes 8..23 now hold K'^T columns in r; lane 24 holds v.

        // ---- h_new directly on lanes 8..23 (no sKT round-trip) ----
        if (l >= 8 && l < 24) {
            int n = l - 8;
            ulonglong2 e0 = *(const ulonglong2*)&se[0];
            ulonglong2 e1 = *(const ulonglong2*)&se[4];
            ull acc = ffma2(pk2(r[0], r[1]), e0.x,
                      ffma2(pk2(r[2], r[3]), e0.y,
                      ffma2(pk2(r[4], r[5]), e1.x,
                      ffma2(pk2(r[6], r[7]), e1.y, 0))));
            hh[n] = hp[n] + sum2(acc);
        }
        if (l == 24) {
            float quad = 0.f;
#pragma unroll
            for (int d = 0; d < 8; d++) quad += se[d] * r[d];
            // Kahan add of quad
            float yk = quad - q_c, tk = q_s + yk;
            q_c = (tk - q_s) - yk; q_s = tk;
            // logdet: accumulate det product in (mantissa, exponent) form
            int e1i; float m1f = frexpf(pprod, &e1i);
            int e2i; mant = frexpf(mant * m1f, &e2i);
            eacc += e1i + e2i;
        }

        // ---- P_new: K' column i2 fetched via shfl from lane 8+i2 ----
        {
            float m0 = __shfl_sync(FULL, r[0], 8 + i2);
            float m1 = __shfl_sync(FULL, r[1], 8 + i2);
            float m2 = __shfl_sync(FULL, r[2], 8 + i2);
            float m3 = __shfl_sync(FULL, r[3], 8 + i2);
            float m4 = __shfl_sync(FULL, r[4], 8 + i2);
            float m5 = __shfl_sync(FULL, r[5], 8 + i2);
            float m6 = __shfl_sync(FULL, r[6], 8 + i2);
            float m7 = __shfl_sync(FULL, r[7], 8 + i2);
            ull K0 = pk2(m0, m1), K1 = pk2(m2, m3);
            ull K2 = pk2(m4, m5), K3 = pk2(m6, m7);
            float ezi = rec[i2];
            float qi  = rec[32 + i2];
            float4 ej0 = *(const float4*)&rec[jb];
            float4 ej1 = *(const float4*)&rec[jb + 4];
            float ej[8] = {ej0.x,ej0.y,ej0.z,ej0.w, ej1.x,ej1.y,ej1.z,ej1.w};
            float4 pav = *(const float4*)&sP[i2 * 20 + jb];
            float4 pbv = *(const float4*)&sP[i2 * 20 + jb + 4];
            float pv[8] = {pav.x,pav.y,pav.z,pav.w, pbv.x,pbv.y,pbv.z,pbv.w};
            float o[8];
#pragma unroll
            for (int u = 0; u < 8; u++) {
                int j = jb + u;
                ulonglong2 c0 = *(const ulonglong2*)&sCPT[j * 12];
                ulonglong2 c1 = *(const ulonglong2*)&sCPT[j * 12 + 4];
                ull acc = ffma2(K0, c0.x, ffma2(K1, c0.y,
                          ffma2(K2, c1.x, ffma2(K3, c1.y, 0))));
                o[u] = ezi * ej[u] * pv[u] - sum2(acc) + ((i2 == j) ? qi : 0.f);
            }
            *(float4*)&sP[i2 * 20 + jb]     = make_float4(o[0], o[1], o[2], o[3]);
            *(float4*)&sP[i2 * 20 + jb + 4] = make_float4(o[4], o[5], o[6], o[7]);
        }
        // stage next record into the other buffer (visible after loop-top sync)
        *(float4*)(&rnx[l * 8])     = pfa;
        *(float4*)(&rnx[l * 8 + 4]) = pfb;
    }
    if (l == 24) {
        float logdet_sum = logf(mant) + (float)eacc * LN2F;
        g_llsum[b] = -0.5f * (logdet_sum + q_s + (float)TT * (float)DY * LOG2PI);
    }
}

__global__ void phase3_kernel(float* __restrict__ out) {
    float v = g_llsum[threadIdx.x];
#pragma unroll
    for (int o = 16; o > 0; o >>= 1) v += __shfl_down_sync(0xffffffffu, v, o);
    if (threadIdx.x == 0) {
        size_t off = (size_t)2 * BB * TT * DY;
        out[off]     = -v / (float)BB;
        out[off + 1] =  v / (float)(BB * TT);
    }
}

extern "C" void kernel_launch(void* const* d_in, const int* in_sizes, int n_in,
                              void* d_out, int out_size) {
    const float* x_feat = (const float*)d_in[0];
    const float* y      = (const float*)d_in[1];
    const float* a_raw  = (const float*)d_in[2];
    const float* W_gate = (const float*)d_in[3];
    const float* b_gate = (const float*)d_in[4];
    const float* W_B    = (const float*)d_in[5];
    const float* b_B    = (const float*)d_in[6];
    const float* W_C    = (const float*)d_in[7];
    const float* b_C    = (const float*)d_in[8];
    const float* W_sig  = (const float*)d_in[9];
    const float* b_sig  = (const float*)d_in[10];
    const float* W_R    = (const float*)d_in[11];
    const float* b_R    = (const float*)d_in[12];
    const float* p0     = (const float*)d_in[13];
    float* out = (float*)d_out;

    void* flag_ptr = nullptr;
    cudaGetSymbolAddress(&flag_ptr, g_flag);
    cudaMemsetAsync(flag_ptr, 0, BB * NCHUNK * sizeof(int), 0);

    cudaFuncSetAttribute(fused_kernel,
                         cudaFuncAttributeMaxDynamicSharedMemorySize, SM_BYTES);
    fused_kernel<<<BB + (BB * TT) / NTOK, 512, SM_BYTES>>>(
        x_feat, y, a_raw, W_gate, b_gate, W_B, b_B, W_C, b_C,
        W_sig, b_sig, W_R, b_R, p0, out);
    phase3_kernel<<<1, 32>>>(out);
}

// round 12
// speedup vs baseline: 1.1906x; 1.0503x over previous
#include <cuda_runtime.h>
#include <math.h>

#define BB 32
#define TT 2048
#define DF 128
#define NN 16
#define DY 8
#define RECSZ 256
#define NTOK 32
#define NCHUNK 64                 // TT / NTOK
#define LOG2PI 1.8378770664093455f
#define LN2F 0.6931471805599453f

__device__ float g_rec[(size_t)BB * TT * RECSZ];   // zero-init; pad [192,256) never written
__device__ float g_llsum[BB];
__device__ int   g_flag[BB * NCHUNK];              // memset to 0 each launch

typedef unsigned long long ull;

__device__ __forceinline__ ull pk2(float a, float b) {
    ull r; asm("mov.b64 %0, {%1,%2};" : "=l"(r) : "f"(a), "f"(b)); return r;
}
__device__ __forceinline__ float sum2(ull v) {
    float a, b; asm("mov.b64 {%0,%1}, %2;" : "=f"(a), "=f"(b) : "l"(v)); return a + b;
}
__device__ __forceinline__ ull ffma2(ull a, ull b, ull c) {
    ull d; asm("fma.rn.f32x2 %0, %1, %2, %3;" : "=l"(d) : "l"(a), "l"(b), "l"(c)); return d;
}
__device__ __forceinline__ ull fadd2(ull a, ull b) {
    ull d; asm("add.rn.f32x2 %0, %1, %2;" : "=l"(d) : "l"(a), "l"(b)); return d;
}
__device__ __forceinline__ float frcp(float x) {
    float r; asm("rcp.approx.f32 %0, %1;" : "=f"(r) : "f"(x)); return r;
}
__device__ __forceinline__ void cp16(float* s, const void* g) {
    unsigned a = (unsigned)__cvta_generic_to_shared(s);
    asm volatile("cp.async.cg.shared.global [%0], [%1], 16;" :: "r"(a), "l"(g));
}
__device__ __forceinline__ void cpcommit() { asm volatile("cp.async.commit_group;"); }
template<int N> __device__ __forceinline__ void cpwait() {
    asm volatile("cp.async.wait_group %0;" :: "n"(N));
}

__device__ __forceinline__ float sp(float x) {
    return fmaxf(x, 0.f) + log1pf(expf(-fabsf(x)));
}
__device__ __forceinline__ float phik(float z, float k) {
    float kz = k * z;
    if (fabsf(kz) < 1e-4f) return 1.f + 0.5f * kz;
    return expm1f(kz) / kz;
}

__device__ __forceinline__ ull dot64(const float* __restrict__ row, const ull* xr2) {
    ull a0 = 0, a1 = 0, a2 = 0, a3 = 0;
#pragma unroll
    for (int k = 0; k < 8; k++) {
        ulonglong2 w0 = *(const ulonglong2*)(row + 8 * k);
        ulonglong2 w1 = *(const ulonglong2*)(row + 8 * k + 4);
        a0 = ffma2(w0.x, xr2[4 * k + 0], a0);
        a1 = ffma2(w0.y, xr2[4 * k + 1], a1);
        a2 = ffma2(w1.x, xr2[4 * k + 2], a2);
        a3 = ffma2(w1.y, xr2[4 * k + 3], a3);
    }
    return fadd2(fadd2(a0, a2), fadd2(a1, a3));
}

// producer dynamic smem layout (float offsets)
#define SM_SX    0
#define SM_SPART 4224
#define SM_SSML  12416
#define SM_W0    14080
#define SM_W1    30464
#define SM_TOT   46848
#define SM_BYTES (SM_TOT * 4)

__device__ __forceinline__ void stageW512(const float* src, float* dst, int tid) {
    const float4* s4 = (const float4*)src;
#pragma unroll
    for (int i = 0; i < 8; i++) {
        int idx = tid + i * 512;
        cp16(dst + idx * 4, s4 + idx);
    }
}

// ---------------------------------------------------------------------------
// Fused kernel: blocks 0..31 = scanners (1 warp), blocks 32.. = producers.
// ---------------------------------------------------------------------------
__global__ __launch_bounds__(512, 1) void fused_kernel(
    const float* __restrict__ x, const float* __restrict__ y,
    const float* __restrict__ a_raw,
    const float* __restrict__ Wg, const float* __restrict__ bg,
    const float* __restrict__ WB, const float* __restrict__ bB,
    const float* __restrict__ WC, const float* __restrict__ bC,
    const float* __restrict__ Ws, const float* __restrict__ bs,
    const float* __restrict__ WR, const float* __restrict__ bR,
    const float* __restrict__ p0, float* __restrict__ out)
{
    // ---- scanner static smem ----
    __shared__ __align__(16) float rec2[2][RECSZ];
    __shared__ __align__(16) float sP[320], sAug[8 * 36], sCPT[192];
    __shared__ __align__(16) float se[8], hh[16], hp[16];

    if (blockIdx.x >= BB) {
        // ================= PRODUCER =================
        extern __shared__ float dsm[];
        float* sx    = dsm + SM_SX;
        float* spart = dsm + SM_SPART;
        float* ssml  = dsm + SM_SSML;
        float* sW0   = dsm + SM_W0;
        float* sW1   = dsm + SM_W1;

        const int tid = threadIdx.x;
        const int warp = tid >> 5, l = tid & 31;
        const int wf = warp & 7, half = warp >> 3;
        const int co = half * 64;
        const int p = blockIdx.x - BB;
        const int batch = p & 31, tchunk = p >> 5;         // time-major order
        const size_t base = (size_t)batch * TT + (size_t)tchunk * NTOK;

        stageW512(WB, sW0, tid);
        cpcommit();

        for (int k = tid; k < NTOK * DF; k += 512) {
            int tok = k >> 7, g = k & 127;
            sx[tok * 132 + g] = x[(base + tok) * DF + g];
        }
        __syncthreads();

        ull xr2[32];
#pragma unroll
        for (int k = 0; k < 16; k++) {
            ulonglong2 v = *(const ulonglong2*)(sx + l * 132 + co + 4 * k);
            xr2[2 * k] = v.x; xr2[2 * k + 1] = v.y;
        }

#pragma unroll
        for (int rr = 0; rr < 4; rr++) {
            int r = wf + 8 * rr;
            if (r < 25) {
                const float* Wrow; float bias;
                if (r == 0)      { Wrow = Wg;                 bias = bg[0]; }
                else if (r < 17) { Wrow = Ws + (r - 1) * DF;  bias = bs[r - 1]; }
                else             { Wrow = WR + (r - 17) * DF; bias = bR[r - 17]; }
                float v = sum2(dot64(Wrow + co, xr2));
                if (half == 0) v += bias;
                ssml[r * 66 + half * 33 + l] = v;
            }
        }

        for (int n = 0; n < NN; n++) {
            float* cur = (n & 1) ? sW1 : sW0;
            float* nxt = (n & 1) ? sW0 : sW1;
            __syncthreads();
            if (n < 15) { stageW512(WB + (size_t)(n + 1) * 16384, nxt, tid); cpcommit(); cpwait<1>(); }
            else        { cpwait<0>(); }
            __syncthreads();

            ull accn2 = 0;
            float bacc = 0.f;
#pragma unroll 4
            for (int fi = 0; fi < 16; fi++) {
                int f = wf + 8 * fi;
                ull rp = dot64(cur + f * 128 + co, xr2);
                float xf = sx[l * 132 + f];
                accn2 = ffma2(pk2(xf, xf), rp, accn2);
                if (half == 0) bacc += xf * bB[n * 128 + f];
            }
            spart[warp * 512 + n * 32 + l] = sum2(accn2) + bacc;
        }
        __syncthreads();

        stageW512(WC, sW0, tid);
        cpcommit();

        {
            int tok = tid & 31, n = tid >> 5;
            float hsum = 0.f;
#pragma unroll
            for (int w2 = 0; w2 < 16; w2++) hsum += spart[w2 * 512 + n * 32 + tok];
            float gate = ssml[tok] + ssml[33 + tok];
            float Delta = sp(gate) + 1e-6f;
            Delta = fminf(fmaxf(Delta, 1e-3f), 1.0f);
            float a = -(sp(a_raw[n]) + 1e-6f);
            float z = fminf(fmaxf(Delta * a, -20.f), 20.f);
            float ez  = expf(z);
            float gam = phik(z, 1.f);
            float rho = phik(z, 2.f);
            float sg = sp(ssml[(1 + n) * 66 + tok] + ssml[(1 + n) * 66 + 33 + tok]) + 1e-6f + 1e-3f;
            size_t rb = (base + tok) * RECSZ;
            g_rec[rb + n]      = ez;
            g_rec[rb + 16 + n] = gam * Delta * hsum;
            g_rec[rb + 32 + n] = sg * sg * rho * Delta;
            if (n < DY) {
                g_rec[rb + 176 + n] = sp(ssml[(17 + n) * 66 + tok] + ssml[(17 + n) * 66 + 33 + tok])
                                      + 1e-6f + 1e-4f;
                g_rec[rb + 184 + n] = y[(base + tok) * DY + n];
            }
        }
        cpwait<0>();
        __syncthreads();

#pragma unroll 4
        for (int jj = 0; jj < 16; jj++) {
            int j = wf * 16 + jj;
            spart[j * 64 + half * 32 + l] = sum2(dot64(sW0 + j * 128 + co, xr2));
        }
        __syncthreads();

        for (int idx = tid; idx < 1024; idx += 512) {
            int tok = idx & 31, j4 = (idx >> 5) * 4;
            float4 v;
            v.x = spart[(j4 + 0) * 64 + tok] + spart[(j4 + 0) * 64 + 32 + tok] + bC[j4 + 0];
            v.y = spart[(j4 + 1) * 64 + tok] + spart[(j4 + 1) * 64 + 32 + tok] + bC[j4 + 1];
            v.z = spart[(j4 + 2) * 64 + tok] + spart[(j4 + 2) * 64 + 32 + tok] + bC[j4 + 2];
            v.w = spart[(j4 + 3) * 64 + tok] + spart[(j4 + 3) * 64 + 32 + tok] + bC[j4 + 3];
            *(float4*)(&g_rec[(base + tok) * RECSZ + 48 + j4]) = v;
        }

        // publish chunk
        __threadfence();
        __syncthreads();
        if (tid == 0) atomicExch(&g_flag[batch * NCHUNK + tchunk], 1);
        return;
    }

    // ================= SCANNER (1 warp per batch) =================
    const int b = blockIdx.x, l = threadIdx.x;
    if (l >= 32) return;
    const unsigned FULL = 0xffffffffu;

    const int i2 = l >> 1, jb = (l & 1) * 8;
    const int d4 = l >> 2, j04 = (l & 3) * 4;

#pragma unroll
    for (int u = 0; u < 8; u++)
        sP[i2 * 20 + jb + u] = (i2 == jb + u) ? fabsf(p0[i2]) : 0.f;
    if (l < 16) hh[l] = 0.f;
    // zero sAug once (junk columns 25..31 stay finite forever)
#pragma unroll
    for (int u = 0; u < 9; u++) sAug[u * 32 + l] = 0.f;
    // lane 24 accumulators: quad sum (Kahan) + logdet product (mant, exp)
    float q_s = 0.f, q_c = 0.f;
    float mant = 1.f; int eacc = 0;

    // wait chunk 0, stage record 0 into buffer 0
    {
        volatile int* f = &g_flag[b * NCHUNK];
        while (*f == 0) __nanosleep(64);
    }
    __threadfence();
    const float* RB = g_rec + (size_t)b * TT * RECSZ;
    {
        float4 a0 = *(const float4*)(RB + l * 8);
        float4 a1 = *(const float4*)(RB + l * 8 + 4);
        *(float4*)(&rec2[0][l * 8])     = a0;
        *(float4*)(&rec2[0][l * 8 + 4]) = a1;
    }

    float* om = out;
    float* ov = out + (size_t)BB * TT * DY;

    for (int t = 0; t < TT; t++) {
        __syncwarp(FULL);           // rec buffer, sP, hh from prev iter visible
        const float* rec = rec2[t & 1];
        float* rnx = rec2[(t + 1) & 1];

        // prefetch next record (LDG issued early, STS at iter bottom)
        float4 pfa, pfb;
        {
            int tn = (t + 1 < TT) ? t + 1 : t;
            if (tn > t && (tn & 31) == 0) {
                volatile int* f = &g_flag[b * NCHUNK + (tn >> 5)];
                while (*f == 0) __nanosleep(64);
                __threadfence();
            }
            const float* nx = RB + (size_t)tn * RECSZ;
            pfa = *(const float4*)(nx + l * 8);
            pfb = *(const float4*)(nx + l * 8 + 4);
        }

        // ---- stage A: hp (all lanes, redundant x2) + CP ----
        {
            int n = l & 15;
            hp[n] = rec[n] * hh[n] + rec[16 + n];
        }
        {
            float4 ez0 = *(const float4*)&rec[0];
            float4 ez1 = *(const float4*)&rec[4];
            float4 ez2 = *(const float4*)&rec[8];
            float4 ez3 = *(const float4*)&rec[12];
            float ezl[16] = {ez0.x,ez0.y,ez0.z,ez0.w, ez1.x,ez1.y,ez1.z,ez1.w,
                             ez2.x,ez2.y,ez2.z,ez2.w, ez3.x,ez3.y,ez3.z,ez3.w};
            const float* Crow = rec + 48 + d4 * 16;
            float4 ca = *(const float4*)(Crow);
            float4 cb = *(const float4*)(Crow + 4);
            float4 cc = *(const float4*)(Crow + 8);
            float4 cd = *(const float4*)(Crow + 12);
            float C[16] = {ca.x,ca.y,ca.z,ca.w, cb.x,cb.y,cb.z,cb.w,
                           cc.x,cc.y,cc.z,cc.w, cd.x,cd.y,cd.z,cd.w};
            float4 qv  = *(const float4*)&rec[32 + j04];
            float4 ezj = *(const float4*)&rec[j04];
            float aA0=0.f,aA1=0.f,aA2=0.f,aA3=0.f;
            float aB0=0.f,aB1=0.f,aB2=0.f,aB3=0.f;
#pragma unroll
            for (int n = 0; n < 16; n += 2) {
                float chA = C[n] * ezl[n];
                float chB = C[n + 1] * ezl[n + 1];
                float4 pA = *(const float4*)&sP[n * 20 + j04];
                float4 pB = *(const float4*)&sP[(n + 1) * 20 + j04];
                aA0 += chA * pA.x; aA1 += chA * pA.y; aA2 += chA * pA.z; aA3 += chA * pA.w;
                aB0 += chB * pB.x; aB1 += chB * pB.y; aB2 += chB * pB.z; aB3 += chB * pB.w;
            }
            float4 cp;
            cp.x = ezj.x * (aA0 + aB0) + C[j04 + 0] * qv.x;
            cp.y = ezj.y * (aA1 + aB1) + C[j04 + 1] * qv.y;
            cp.z = ezj.z * (aA2 + aB2) + C[j04 + 2] * qv.z;
            cp.w = ezj.w * (aA3 + aB3) + C[j04 + 3] * qv.w;
            *(float4*)&sAug[d4 * 36 + 8 + j04] = cp;
            sCPT[(j04 + 0) * 12 + d4] = cp.x;
            sCPT[(j04 + 1) * 12 + d4] = cp.y;
            sCPT[(j04 + 2) * 12 + d4] = cp.z;
            sCPT[(j04 + 3) * 12 + d4] = cp.w;
        }
        __syncwarp(FULL);

        // ---- stage B: S (2 per lane, diag -> ov direct) + y_pred (all lanes, x4) ----
        {
            int d = d4, q0 = (l & 3) * 2;
            ulonglong2 g0 = *(const ulonglong2*)&sAug[d * 36 + 8];
            ulonglong2 g1 = *(const ulonglong2*)&sAug[d * 36 + 12];
            ulonglong2 g2 = *(const ulonglong2*)&sAug[d * 36 + 16];
            ulonglong2 g3 = *(const ulonglong2*)&sAug[d * 36 + 20];
#pragma unroll
            for (int qq = 0; qq < 2; qq++) {
                int q = q0 + qq;
                ulonglong2 c0 = *(const ulonglong2*)&rec[48 + q * 16];
                ulonglong2 c1 = *(const ulonglong2*)&rec[48 + q * 16 + 4];
                ulonglong2 c2 = *(const ulonglong2*)&rec[48 + q * 16 + 8];
                ulonglong2 c3 = *(const ulonglong2*)&rec[48 + q * 16 + 12];
                ull x0 = ffma2(g0.x, c0.x, ffma2(g0.y, c0.y, 0));
                ull x1 = ffma2(g1.x, c1.x, ffma2(g1.y, c1.y, 0));
                ull x2 = ffma2(g2.x, c2.x, ffma2(g2.y, c2.y, 0));
                ull x3 = ffma2(g3.x, c3.x, ffma2(g3.y, c3.y, 0));
                float s = sum2(fadd2(fadd2(x0, x1), fadd2(x2, x3)));
                if (d == q) {
                    s += rec[176 + d];
                    ov[((size_t)b * TT + t) * DY + d] = s;   // S diag out, direct
                }
                sAug[d * 36 + q] = s;
            }
            // y_pred/e: all lanes compute (dd = l&7, 4x redundant), lanes 24..31 store
            int dd = l & 7;
            float yp = 0.f;
#pragma unroll
            for (int n = 0; n < 16; n++) yp += rec[48 + dd * 16 + n] * hp[n];
            float ee = rec[184 + dd] - yp;
            if (l >= 24) {
                om[((size_t)b * TT + t) * DY + dd] = yp;     // y_pred out, direct
                se[dd] = ee;
                sAug[dd * 36 + 24] = ee;
            }
        }
        __syncwarp(FULL);

        // ---- stage C: 2x2 block Gauss-Jordan on sAug columns, lane = column ----
        float r[8];
#pragma unroll
        for (int d = 0; d < 8; d++) r[d] = sAug[d * 36 + l];
        float pprod = 1.f;
#pragma unroll
        for (int k = 0; k < 4; k++) {
            const int p0i = 2 * k, p1i = 2 * k + 1;
            float r0 = r[p0i], r1 = r[p1i];
            float pa = __shfl_sync(FULL, r0, p0i);   // A[p0][p0]
            float pc = __shfl_sync(FULL, r1, p0i);   // A[p1][p0]
            float pb = __shfl_sync(FULL, r0, p1i);   // A[p0][p1]
            float pd = __shfl_sync(FULL, r1, p1i);   // A[p1][p1]
            float det = pa * pd - pb * pc;
            pprod *= det;
            float rdet = frcp(det);
            float n0 = rdet * (pd * r0 - pb * r1);
            float n1 = rdet * (pa * r1 - pc * r0);
#pragma unroll
            for (int i = 0; i < 8; i++) {
                if (i == p0i || i == p1i) continue;
                float m0 = __shfl_sync(FULL, r[i], p0i);
                float m1 = __shfl_sync(FULL, r[i], p1i);
                r[i] -= m0 * n0 + m1 * n1;
            }
            r[p0i] = n0; r[p1i] = n1;
        }
        // lanes 8..23 now hold K'^T columns in r; lane 24 holds v.

        // ---- h_new directly on lanes 8..23 (no sKT round-trip) ----
        if (l >= 8 && l < 24) {
            int n = l - 8;
            ulonglong2 e0 = *(const ulonglong2*)&se[0];
            ulonglong2 e1 = *(const ulonglong2*)&se[4];
            ull acc = ffma2(pk2(r[0], r[1]), e0.x,
                      ffma2(pk2(r[2], r[3]), e0.y,
                      ffma2(pk2(r[4], r[5]), e1.x,
                      ffma2(pk2(r[6], r[7]), e1.y, 0))));
            hh[n] = hp[n] + sum2(acc);
        }
        if (l == 24) {
            float quad = 0.f;
#pragma unroll
            for (int d = 0; d < 8; d++) quad += se[d] * r[d];
            // Kahan add of quad
            float yk = quad - q_c, tk = q_s + yk;
            q_c = (tk - q_s) - yk; q_s = tk;
            // logdet: accumulate det product in (mantissa, exponent) form
            int e1i; float m1f = frexpf(pprod, &e1i);
            int e2i; mant = frexpf(mant * m1f, &e2i);
            eacc += e1i + e2i;
        }

        // ---- P_new: K' column i2 fetched via shfl from lane 8+i2 ----
        {
            float m0 = __shfl_sync(FULL, r[0], 8 + i2);
            float m1 = __shfl_sync(FULL, r[1], 8 + i2);
            float m2 = __shfl_sync(FULL, r[2], 8 + i2);
            float m3 = __shfl_sync(FULL, r[3], 8 + i2);
            float m4 = __shfl_sync(FULL, r[4], 8 + i2);
            float m5 = __shfl_sync(FULL, r[5], 8 + i2);
            float m6 = __shfl_sync(FULL, r[6], 8 + i2);
            float m7 = __shfl_sync(FULL, r[7], 8 + i2);
            ull K0 = pk2(m0, m1), K1 = pk2(m2, m3);
            ull K2 = pk2(m4, m5), K3 = pk2(m6, m7);
            float ezi = rec[i2];
            float qi  = rec[32 + i2];
            float4 ej0 = *(const float4*)&rec[jb];
            float4 ej1 = *(const float4*)&rec[jb + 4];
            float ej[8] = {ej0.x,ej0.y,ej0.z,ej0.w, ej1.x,ej1.y,ej1.z,ej1.w};
            float4 pav = *(const float4*)&sP[i2 * 20 + jb];
            float4 pbv = *(const float4*)&sP[i2 * 20 + jb + 4];
            float pv[8] = {pav.x,pav.y,pav.z,pav.w, pbv.x,pbv.y,pbv.z,pbv.w};
            float o[8];
#pragma unroll
            for (int u = 0; u < 8; u++) {
                int j = jb + u;
                ulonglong2 c0 = *(const ulonglong2*)&sCPT[j * 12];
                ulonglong2 c1 = *(const ulonglong2*)&sCPT[j * 12 + 4];
                ull acc = ffma2(K0, c0.x, ffma2(K1, c0.y,
                          ffma2(K2, c1.x, ffma2(K3, c1.y, 0))));
                o[u] = ezi * ej[u] * pv[u] - sum2(acc) + ((i2 == j) ? qi : 0.f);
            }
            *(float4*)&sP[i2 * 20 + jb]     = make_float4(o[0], o[1], o[2], o[3]);
            *(float4*)&sP[i2 * 20 + jb + 4] = make_float4(o[4], o[5], o[6], o[7]);
        }
        // stage next record into the other buffer (visible after loop-top sync)
        *(float4*)(&rnx[l * 8])     = pfa;
        *(float4*)(&rnx[l * 8 + 4]) = pfb;
    }
    if (l == 24) {
        float logdet_sum = logf(mant) + (float)eacc * LN2F;
        g_llsum[b] = -0.5f * (logdet_sum + q_s + (float)TT * (float)DY * LOG2PI);
    }
}

__global__ void phase3_kernel(float* __restrict__ out) {
    float v = g_llsum[threadIdx.x];
#pragma unroll
    for (int o = 16; o > 0; o >>= 1) v += __shfl_down_sync(0xffffffffu, v, o);
    if (threadIdx.x == 0) {
        size_t off = (size_t)2 * BB * TT * DY;
        out[off]     = -v / (float)BB;
        out[off + 1] =  v / (float)(BB * TT);
    }
}

extern "C" void kernel_launch(void* const* d_in, const int* in_sizes, int n_in,
                              void* d_out, int out_size) {
    const float* x_feat = (const float*)d_in[0];
    const float* y      = (const float*)d_in[1];
    const float* a_raw  = (const float*)d_in[2];
    const float* W_gate = (const float*)d_in[3];
    const float* b_gate = (const float*)d_in[4];
    const float* W_B    = (const float*)d_in[5];
    const float* b_B    = (const float*)d_in[6];
    const float* W_C    = (const float*)d_in[7];
    const float* b_C    = (const float*)d_in[8];
    const float* W_sig  = (const float*)d_in[9];
    const float* b_sig  = (const float*)d_in[10];
    const float* W_R    = (const float*)d_in[11];
    const float* b_R    = (const float*)d_in[12];
    const float* p0     = (const float*)d_in[13];
    float* out = (float*)d_out;

    void* flag_ptr = nullptr;
    cudaGetSymbolAddress(&flag_ptr, g_flag);
    cudaMemsetAsync(flag_ptr, 0, BB * NCHUNK * sizeof(int), 0);

    cudaFuncSetAttribute(fused_kernel,
                         cudaFuncAttributeMaxDynamicSharedMemorySize, SM_BYTES);
    fused_kernel<<<BB + (BB * TT) / NTOK, 512, SM_BYTES>>>(
        x_feat, y, a_raw, W_gate, b_gate, W_B, b_B, W_C, b_C,
        W_sig, b_sig, W_R, b_R, p0, out);
    phase3_kernel<<<1, 32>>>(out);
}

// round 14
// speedup vs baseline: 1.2344x; 1.0368x over previous
#include <cuda_runtime.h>
#include <math.h>

#define BB 32
#define TT 2048
#define DF 128
#define NN 16
#define DY 8
#define RECSZ 256
#define NTOK 32
#define NCHUNK 64                 // TT / NTOK
#define LOG2PI 1.8378770664093455f
#define LN2F 0.6931471805599453f

__device__ float g_rec[(size_t)BB * TT * RECSZ];   // zero-init; pad [192,256) never written
__device__ float g_llsum[BB];
__device__ int   g_flag[BB * NCHUNK];              // memset to 0 each launch

typedef unsigned long long ull;

__device__ __forceinline__ ull pk2(float a, float b) {
    ull r; asm("mov.b64 %0, {%1,%2};" : "=l"(r) : "f"(a), "f"(b)); return r;
}
__device__ __forceinline__ float sum2(ull v) {
    float a, b; asm("mov.b64 {%0,%1}, %2;" : "=f"(a), "=f"(b) : "l"(v)); return a + b;
}
__device__ __forceinline__ void unpk2(ull v, float& a, float& b) {
    asm("mov.b64 {%0,%1}, %2;" : "=f"(a), "=f"(b) : "l"(v));
}
__device__ __forceinline__ ull ffma2(ull a, ull b, ull c) {
    ull d; asm("fma.rn.f32x2 %0, %1, %2, %3;" : "=l"(d) : "l"(a), "l"(b), "l"(c)); return d;
}
__device__ __forceinline__ ull fmul2(ull a, ull b) {
    ull d; asm("mul.rn.f32x2 %0, %1, %2;" : "=l"(d) : "l"(a), "l"(b)); return d;
}
__device__ __forceinline__ ull fadd2(ull a, ull b) {
    ull d; asm("add.rn.f32x2 %0, %1, %2;" : "=l"(d) : "l"(a), "l"(b)); return d;
}
__device__ __forceinline__ float frcp(float x) {
    float r; asm("rcp.approx.f32 %0, %1;" : "=f"(r) : "f"(x)); return r;
}
__device__ __forceinline__ void cp16(float* s, const void* g) {
    unsigned a = (unsigned)__cvta_generic_to_shared(s);
    asm volatile("cp.async.cg.shared.global [%0], [%1], 16;" :: "r"(a), "l"(g));
}
__device__ __forceinline__ void cpcommit() { asm volatile("cp.async.commit_group;"); }
template<int N> __device__ __forceinline__ void cpwait() {
    asm volatile("cp.async.wait_group %0;" :: "n"(N));
}

__device__ __forceinline__ float sp(float x) {
    return fmaxf(x, 0.f) + log1pf(expf(-fabsf(x)));
}
__device__ __forceinline__ float phik(float z, float k) {
    float kz = k * z;
    if (fabsf(kz) < 1e-4f) return 1.f + 0.5f * kz;
    return expm1f(kz) / kz;
}

__device__ __forceinline__ ull dot64(const float* __restrict__ row, const ull* xr2) {
    ull a0 = 0, a1 = 0, a2 = 0, a3 = 0;
#pragma unroll
    for (int k = 0; k < 8; k++) {
        ulonglong2 w0 = *(const ulonglong2*)(row + 8 * k);
        ulonglong2 w1 = *(const ulonglong2*)(row + 8 * k + 4);
        a0 = ffma2(w0.x, xr2[4 * k + 0], a0);
        a1 = ffma2(w0.y, xr2[4 * k + 1], a1);
        a2 = ffma2(w1.x, xr2[4 * k + 2], a2);
        a3 = ffma2(w1.y, xr2[4 * k + 3], a3);
    }
    return fadd2(fadd2(a0, a2), fadd2(a1, a3));
}

// producer dynamic smem layout (float offsets)
#define SM_SX    0
#define SM_SPART 4224
#define SM_SSML  12416
#define SM_W0    14080
#define SM_W1    30464
#define SM_TOT   46848
#define SM_BYTES (SM_TOT * 4)

__device__ __forceinline__ void stageW512(const float* src, float* dst, int tid) {
    const float4* s4 = (const float4*)src;
#pragma unroll
    for (int i = 0; i < 8; i++) {
        int idx = tid + i * 512;
        cp16(dst + idx * 4, s4 + idx);
    }
}

// ---------------------------------------------------------------------------
// Fused kernel: blocks 0..31 = scanners (1 warp), blocks 32.. = producers.
// ---------------------------------------------------------------------------
__global__ __launch_bounds__(512, 1) void fused_kernel(
    const float* __restrict__ x, const float* __restrict__ y,
    const float* __restrict__ a_raw,
    const float* __restrict__ Wg, const float* __restrict__ bg,
    const float* __restrict__ WB, const float* __restrict__ bB,
    const float* __restrict__ WC, const float* __restrict__ bC,
    const float* __restrict__ Ws, const float* __restrict__ bs,
    const float* __restrict__ WR, const float* __restrict__ bR,
    const float* __restrict__ p0, float* __restrict__ out)
{
    // ---- scanner static smem ----
    __shared__ __align__(16) float rec2[2][RECSZ];
    __shared__ __align__(16) float sP[320], sAug[8 * 36], sCPT[192];
    __shared__ __align__(16) float se[8], hh[16], hp[16];

    if (blockIdx.x >= BB) {
        // ================= PRODUCER =================
        extern __shared__ float dsm[];
        float* sx    = dsm + SM_SX;
        float* spart = dsm + SM_SPART;
        float* ssml  = dsm + SM_SSML;
        float* sW0   = dsm + SM_W0;
        float* sW1   = dsm + SM_W1;

        const int tid = threadIdx.x;
        const int warp = tid >> 5, l = tid & 31;
        const int wf = warp & 7, half = warp >> 3;
        const int co = half * 64;
        const int p = blockIdx.x - BB;
        const int batch = p & 31, tchunk = p >> 5;         // time-major order
        const size_t base = (size_t)batch * TT + (size_t)tchunk * NTOK;

        stageW512(WB, sW0, tid);
        cpcommit();

        for (int k = tid; k < NTOK * DF; k += 512) {
            int tok = k >> 7, g = k & 127;
            sx[tok * 132 + g] = x[(base + tok) * DF + g];
        }
        __syncthreads();

        ull xr2[32];
#pragma unroll
        for (int k = 0; k < 16; k++) {
            ulonglong2 v = *(const ulonglong2*)(sx + l * 132 + co + 4 * k);
            xr2[2 * k] = v.x; xr2[2 * k + 1] = v.y;
        }

#pragma unroll
        for (int rr = 0; rr < 4; rr++) {
            int r = wf + 8 * rr;
            if (r < 25) {
                const float* Wrow; float bias;
                if (r == 0)      { Wrow = Wg;                 bias = bg[0]; }
                else if (r < 17) { Wrow = Ws + (r - 1) * DF;  bias = bs[r - 1]; }
                else             { Wrow = WR + (r - 17) * DF; bias = bR[r - 17]; }
                float v = sum2(dot64(Wrow + co, xr2));
                if (half == 0) v += bias;
                ssml[r * 66 + half * 33 + l] = v;
            }
        }

        for (int n = 0; n < NN; n++) {
            float* cur = (n & 1) ? sW1 : sW0;
            float* nxt = (n & 1) ? sW0 : sW1;
            __syncthreads();
            if (n < 15) { stageW512(WB + (size_t)(n + 1) * 16384, nxt, tid); cpcommit(); cpwait<1>(); }
            else        { cpwait<0>(); }
            __syncthreads();

            ull accn2 = 0;
            float bacc = 0.f;
#pragma unroll 4
            for (int fi = 0; fi < 16; fi++) {
                int f = wf + 8 * fi;
                ull rp = dot64(cur + f * 128 + co, xr2);
                float xf = sx[l * 132 + f];
                accn2 = ffma2(pk2(xf, xf), rp, accn2);
                if (half == 0) bacc += xf * bB[n * 128 + f];
            }
            spart[warp * 512 + n * 32 + l] = sum2(accn2) + bacc;
        }
        __syncthreads();

        stageW512(WC, sW0, tid);
        cpcommit();

        {
            int tok = tid & 31, n = tid >> 5;
            float hsum = 0.f;
#pragma unroll
            for (int w2 = 0; w2 < 16; w2++) hsum += spart[w2 * 512 + n * 32 + tok];
            float gate = ssml[tok] + ssml[33 + tok];
            float Delta = sp(gate) + 1e-6f;
            Delta = fminf(fmaxf(Delta, 1e-3f), 1.0f);
            float a = -(sp(a_raw[n]) + 1e-6f);
            float z = fminf(fmaxf(Delta * a, -20.f), 20.f);
            float ez  = expf(z);
            float gam = phik(z, 1.f);
            float rho = phik(z, 2.f);
            float sg = sp(ssml[(1 + n) * 66 + tok] + ssml[(1 + n) * 66 + 33 + tok]) + 1e-6f + 1e-3f;
            size_t rb = (base + tok) * RECSZ;
            g_rec[rb + n]      = ez;
            g_rec[rb + 16 + n] = gam * Delta * hsum;
            g_rec[rb + 32 + n] = sg * sg * rho * Delta;
            if (n < DY) {
                g_rec[rb + 176 + n] = sp(ssml[(17 + n) * 66 + tok] + ssml[(17 + n) * 66 + 33 + tok])
                                      + 1e-6f + 1e-4f;
                g_rec[rb + 184 + n] = y[(base + tok) * DY + n];
            }
        }
        cpwait<0>();
        __syncthreads();

#pragma unroll 4
        for (int jj = 0; jj < 16; jj++) {
            int j = wf * 16 + jj;
            spart[j * 64 + half * 32 + l] = sum2(dot64(sW0 + j * 128 + co, xr2));
        }
        __syncthreads();

        for (int idx = tid; idx < 1024; idx += 512) {
            int tok = idx & 31, j4 = (idx >> 5) * 4;
            float4 v;
            v.x = spart[(j4 + 0) * 64 + tok] + spart[(j4 + 0) * 64 + 32 + tok] + bC[j4 + 0];
            v.y = spart[(j4 + 1) * 64 + tok] + spart[(j4 + 1) * 64 + 32 + tok] + bC[j4 + 1];
            v.z = spart[(j4 + 2) * 64 + tok] + spart[(j4 + 2) * 64 + 32 + tok] + bC[j4 + 2];
            v.w = spart[(j4 + 3) * 64 + tok] + spart[(j4 + 3) * 64 + 32 + tok] + bC[j4 + 3];
            *(float4*)(&g_rec[(base + tok) * RECSZ + 48 + j4]) = v;
        }

        // publish chunk
        __threadfence();
        __syncthreads();
        if (tid == 0) atomicExch(&g_flag[batch * NCHUNK + tchunk], 1);
        return;
    }

    // ================= SCANNER (1 warp per batch) =================
    const int b = blockIdx.x, l = threadIdx.x;
    if (l >= 32) return;
    const unsigned FULL = 0xffffffffu;

    const int i2 = l >> 1, jb = (l & 1) * 8;
    const int d4 = l >> 2, j04 = (l & 3) * 4;

#pragma unroll
    for (int u = 0; u < 8; u++)
        sP[i2 * 20 + jb + u] = (i2 == jb + u) ? fabsf(p0[i2]) : 0.f;
    if (l < 16) hh[l] = 0.f;
    // zero sAug once (junk columns 25..31 stay finite forever)
#pragma unroll
    for (int u = 0; u < 9; u++) sAug[u * 32 + l] = 0.f;
    // lane 24 accumulators: quad sum (Kahan) + logdet product (mant, exp)
    float q_s = 0.f, q_c = 0.f;
    float mant = 1.f; int eacc = 0;

    // wait chunk 0, stage record 0 into buffer 0
    {
        volatile int* f = &g_flag[b * NCHUNK];
        while (*f == 0) __nanosleep(64);
    }
    __threadfence();
    const float* RB = g_rec + (size_t)b * TT * RECSZ;
    {
        float4 a0 = *(const float4*)(RB + l * 8);
        float4 a1 = *(const float4*)(RB + l * 8 + 4);
        *(float4*)(&rec2[0][l * 8])     = a0;
        *(float4*)(&rec2[0][l * 8 + 4]) = a1;
    }

    float* om = out;
    float* ov = out + (size_t)BB * TT * DY;

    for (int t = 0; t < TT; t++) {
        __syncwarp(FULL);           // rec buffer, sP, hh from prev iter visible
        const float* rec = rec2[t & 1];
        float* rnx = rec2[(t + 1) & 1];

        // prefetch next record (LDG issued early, STS at iter bottom)
        float4 pfa, pfb;
        {
            int tn = (t + 1 < TT) ? t + 1 : t;
            if (tn > t && (tn & 31) == 0) {
                volatile int* f = &g_flag[b * NCHUNK + (tn >> 5)];
                while (*f == 0) __nanosleep(64);
                __threadfence();
            }
            const float* nx = RB + (size_t)tn * RECSZ;
            pfa = *(const float4*)(nx + l * 8);
            pfb = *(const float4*)(nx + l * 8 + 4);
        }

        // ---- stage A: hp (all lanes, redundant x2) + CP (f32x2) ----
        {
            int n = l & 15;
            hp[n] = rec[n] * hh[n] + rec[16 + n];
        }
        {
            float4 ez0 = *(const float4*)&rec[0];
            float4 ez1 = *(const float4*)&rec[4];
            float4 ez2 = *(const float4*)&rec[8];
            float4 ez3 = *(const float4*)&rec[12];
            float ezl[16] = {ez0.x,ez0.y,ez0.z,ez0.w, ez1.x,ez1.y,ez1.z,ez1.w,
                             ez2.x,ez2.y,ez2.z,ez2.w, ez3.x,ez3.y,ez3.z,ez3.w};
            const float* Crow = rec + 48 + d4 * 16;
            float4 ca = *(const float4*)(Crow);
            float4 cb = *(const float4*)(Crow + 4);
            float4 cc = *(const float4*)(Crow + 8);
            float4 cd = *(const float4*)(Crow + 12);
            float C[16] = {ca.x,ca.y,ca.z,ca.w, cb.x,cb.y,cb.z,cb.w,
                           cc.x,cc.y,cc.z,cc.w, cd.x,cd.y,cd.z,cd.w};
            ull accA = 0, accB = 0;        // cols (j04,j04+1), (j04+2,j04+3)
#pragma unroll
            for (int n = 0; n < 16; n++) {
                float ch = C[n] * ezl[n];
                ull ch2 = pk2(ch, ch);
                ulonglong2 p = *(const ulonglong2*)&sP[n * 20 + j04];
                accA = ffma2(ch2, p.x, accA);
                accB = ffma2(ch2, p.y, accB);
            }
            ulonglong2 ezjp = *(const ulonglong2*)&rec[j04];
            ulonglong2 qvp  = *(const ulonglong2*)&rec[32 + j04];
            ulonglong2 cjp  = *(const ulonglong2*)(Crow + j04);
            ull cp01 = ffma2(cjp.x, qvp.x, fmul2(ezjp.x, accA));
            ull cp23 = ffma2(cjp.y, qvp.y, fmul2(ezjp.y, accB));
            ulonglong2 cps; cps.x = cp01; cps.y = cp23;
            *(ulonglong2*)&sAug[d4 * 36 + 8 + j04] = cps;
            float c0f, c1f, c2f, c3f;
            unpk2(cp01, c0f, c1f); unpk2(cp23, c2f, c3f);
            sCPT[(j04 + 0) * 12 + d4] = c0f;
            sCPT[(j04 + 1) * 12 + d4] = c1f;
            sCPT[(j04 + 2) * 12 + d4] = c2f;
            sCPT[(j04 + 3) * 12 + d4] = c3f;
        }
        __syncwarp(FULL);

        // ---- stage B: S (2 per lane, diag -> ov direct) + y_pred (all lanes, x4, f32x2) ----
        {
            int d = d4, q0 = (l & 3) * 2;
            ulonglong2 g0 = *(const ulonglong2*)&sAug[d * 36 + 8];
            ulonglong2 g1 = *(const ulonglong2*)&sAug[d * 36 + 12];
            ulonglong2 g2 = *(const ulonglong2*)&sAug[d * 36 + 16];
            ulonglong2 g3 = *(const ulonglong2*)&sAug[d * 36 + 20];
#pragma unroll
            for (int qq = 0; qq < 2; qq++) {
                int q = q0 + qq;
                ulonglong2 c0 = *(const ulonglong2*)&rec[48 + q * 16];
                ulonglong2 c1 = *(const ulonglong2*)&rec[48 + q * 16 + 4];
                ulonglong2 c2 = *(const ulonglong2*)&rec[48 + q * 16 + 8];
                ulonglong2 c3 = *(const ulonglong2*)&rec[48 + q * 16 + 12];
                ull x0 = ffma2(g0.x, c0.x, ffma2(g0.y, c0.y, 0));
                ull x1 = ffma2(g1.x, c1.x, ffma2(g1.y, c1.y, 0));
                ull x2 = ffma2(g2.x, c2.x, ffma2(g2.y, c2.y, 0));
                ull x3 = ffma2(g3.x, c3.x, ffma2(g3.y, c3.y, 0));
                float s = sum2(fadd2(fadd2(x0, x1), fadd2(x2, x3)));
                if (d == q) {
                    s += rec[176 + d];
                    ov[((size_t)b * TT + t) * DY + d] = s;   // S diag out, direct
                }
                sAug[d * 36 + q] = s;
            }
            // y_pred/e: all lanes compute (dd = l&7, 4x redundant), lanes 24..31 store
            int dd = l & 7;
            const float* Cd = rec + 48 + dd * 16;
            ulonglong2 cd0 = *(const ulonglong2*)(Cd);
            ulonglong2 cd1 = *(const ulonglong2*)(Cd + 4);
            ulonglong2 cd2 = *(const ulonglong2*)(Cd + 8);
            ulonglong2 cd3 = *(const ulonglong2*)(Cd + 12);
            ulonglong2 h0 = *(const ulonglong2*)&hp[0];
            ulonglong2 h1 = *(const ulonglong2*)&hp[4];
            ulonglong2 h2 = *(const ulonglong2*)&hp[8];
            ulonglong2 h3 = *(const ulonglong2*)&hp[12];
            ull ya = ffma2(cd0.x, h0.x, ffma2(cd0.y, h0.y, 0));
            ull yb = ffma2(cd1.x, h1.x, ffma2(cd1.y, h1.y, 0));
            ull yc = ffma2(cd2.x, h2.x, ffma2(cd2.y, h2.y, 0));
            ull yd = ffma2(cd3.x, h3.x, ffma2(cd3.y, h3.y, 0));
            float yp = sum2(fadd2(fadd2(ya, yb), fadd2(yc, yd)));
            float ee = rec[184 + dd] - yp;
            if (l >= 24) {
                om[((size_t)b * TT + t) * DY + dd] = yp;     // y_pred out, direct
                se[dd] = ee;
                sAug[dd * 36 + 24] = ee;
            }
        }
        __syncwarp(FULL);

        // ---- stage C: 2x2 block Gauss-Jordan on sAug columns, lane = column ----
        float r[8];
#pragma unroll
        for (int d = 0; d < 8; d++) r[d] = sAug[d * 36 + l];
        float pprod = 1.f;
#pragma unroll
        for (int k = 0; k < 4; k++) {
            const int p0i = 2 * k, p1i = 2 * k + 1;
            float r0 = r[p0i], r1 = r[p1i];
            float pa = __shfl_sync(FULL, r0, p0i);   // A[p0][p0]
            float pc = __shfl_sync(FULL, r1, p0i);   // A[p1][p0]
            float pb = __shfl_sync(FULL, r0, p1i);   // A[p0][p1]
            float pd = __shfl_sync(FULL, r1, p1i);   // A[p1][p1]
            float det = pa * pd - pb * pc;
            pprod *= det;
            float rdet = frcp(det);
            float n0 = rdet * (pd * r0 - pb * r1);
            float n1 = rdet * (pa * r1 - pc * r0);
#pragma unroll
            for (int i = 0; i < 8; i++) {
                if (i == p0i || i == p1i) continue;
                float m0 = __shfl_sync(FULL, r[i], p0i);
                float m1 = __shfl_sync(FULL, r[i], p1i);
                r[i] -= m0 * n0 + m1 * n1;
            }
            r[p0i] = n0; r[p1i] = n1;
        }
        // lanes 8..23 now hold K'^T columns in r; lane 24 holds v.

        // ---- h_new directly on lanes 8..23 (no sKT round-trip) ----
        if (l >= 8 && l < 24) {
            int n = l - 8;
            ulonglong2 e0 = *(const ulonglong2*)&se[0];
            ulonglong2 e1 = *(const ulonglong2*)&se[4];
            ull acc = ffma2(pk2(r[0], r[1]), e0.x,
                      ffma2(pk2(r[2], r[3]), e0.y,
                      ffma2(pk2(r[4], r[5]), e1.x,
                      ffma2(pk2(r[6], r[7]), e1.y, 0))));
            hh[n] = hp[n] + sum2(acc);
        }
        if (l == 24) {
            float quad = 0.f;
#pragma unroll
            for (int d = 0; d < 8; d++) quad += se[d] * r[d];
            // Kahan add of quad
            float yk = quad - q_c, tk = q_s + yk;
            q_c = (tk - q_s) - yk; q_s = tk;
            // logdet: accumulate det product in (mantissa, exponent) form
            int e1i; float m1f = frexpf(pprod, &e1i);
            int e2i; mant = frexpf(mant * m1f, &e2i);
            eacc += e1i + e2i;
        }

        // ---- P_new: K' column i2 fetched via shfl from lane 8+i2 ----
        {
            float m0 = __shfl_sync(FULL, r[0], 8 + i2);
            float m1 = __shfl_sync(FULL, r[1], 8 + i2);
            float m2 = __shfl_sync(FULL, r[2], 8 + i2);
            float m3 = __shfl_sync(FULL, r[3], 8 + i2);
            float m4 = __shfl_sync(FULL, r[4], 8 + i2);
            float m5 = __shfl_sync(FULL, r[5], 8 + i2);
            float m6 = __shfl_sync(FULL, r[6], 8 + i2);
            float m7 = __shfl_sync(FULL, r[7], 8 + i2);
            ull K0 = pk2(m0, m1), K1 = pk2(m2, m3);
            ull K2 = pk2(m4, m5), K3 = pk2(m6, m7);
            float ezi = rec[i2];
            float qi  = rec[32 + i2];
            float4 ej0 = *(const float4*)&rec[jb];
            float4 ej1 = *(const float4*)&rec[jb + 4];
            float ej[8] = {ej0.x,ej0.y,ej0.z,ej0.w, ej1.x,ej1.y,ej1.z,ej1.w};
            float4 pav = *(const float4*)&sP[i2 * 20 + jb];
            float4 pbv = *(const float4*)&sP[i2 * 20 + jb + 4];
            float pv[8] = {pav.x,pav.y,pav.z,pav.w, pbv.x,pbv.y,pbv.z,pbv.w};
            float o[8];
#pragma unroll
            for (int u = 0; u < 8; u++) {
                int j = jb + u;
                ulonglong2 c0 = *(const ulonglong2*)&sCPT[j * 12];
                ulonglong2 c1 = *(const ulonglong2*)&sCPT[j * 12 + 4];
                ull acc = ffma2(K0, c0.x, ffma2(K1, c0.y,
                          ffma2(K2, c1.x, ffma2(K3, c1.y, 0))));
                o[u] = ezi * ej[u] * pv[u] - sum2(acc) + ((i2 == j) ? qi : 0.f);
            }
            *(float4*)&sP[i2 * 20 + jb]     = make_float4(o[0], o[1], o[2], o[3]);
            *(float4*)&sP[i2 * 20 + jb + 4] = make_float4(o[4], o[5], o[6], o[7]);
        }
        // stage next record into the other buffer (visible after loop-top sync)
        *(float4*)(&rnx[l * 8])     = pfa;
        *(float4*)(&rnx[l * 8 + 4]) = pfb;
    }
    if (l == 24) {
        float logdet_sum = logf(mant) + (float)eacc * LN2F;
        g_llsum[b] = -0.5f * (logdet_sum + q_s + (float)TT * (float)DY * LOG2PI);
    }
}

__global__ void phase3_kernel(float* __restrict__ out) {
    float v = g_llsum[threadIdx.x];
#pragma unroll
    for (int o = 16; o > 0; o >>= 1) v += __shfl_down_sync(0xffffffffu, v, o);
    if (threadIdx.x == 0) {
        size_t off = (size_t)2 * BB * TT * DY;
        out[off]     = -v / (float)BB;
        out[off + 1] =  v / (float)(BB * TT);
    }
}

extern "C" void kernel_launch(void* const* d_in, const int* in_sizes, int n_in,
                              void* d_out, int out_size) {
    const float* x_feat = (const float*)d_in[0];
    const float* y      = (const float*)d_in[1];
    const float* a_raw  = (const float*)d_in[2];
    const float* W_gate = (const float*)d_in[3];
    const float* b_gate = (const float*)d_in[4];
    const float* W_B    = (const float*)d_in[5];
    const float* b_B    = (const float*)d_in[6];
    const float* W_C    = (const float*)d_in[7];
    const float* b_C    = (const float*)d_in[8];
    const float* W_sig  = (const float*)d_in[9];
    const float* b_sig  = (const float*)d_in[10];
    const float* W_R    = (const float*)d_in[11];
    const float* b_R    = (const float*)d_in[12];
    const float* p0     = (const float*)d_in[13];
    float* out = (float*)d_out;

    void* flag_ptr = nullptr;
    cudaGetSymbolAddress(&flag_ptr, g_flag);
    cudaMemsetAsync(flag_ptr, 0, BB * NCHUNK * sizeof(int), 0);

    cudaFuncSetAttribute(fused_kernel,
                         cudaFuncAttributeMaxDynamicSharedMemorySize, SM_BYTES);
    fused_kernel<<<BB + (BB * TT) / NTOK, 512, SM_BYTES>>>(
        x_feat, y, a_raw, W_gate, b_gate, W_B, b_B, W_C, b_C,
        W_sig, b_sig, W_R, b_R, p0, out);
    phase3_kernel<<<1, 32>>>(out);
}

// round 16
// speedup vs baseline: 1.2873x; 1.0429x over previous
#include <cuda_runtime.h>
#include <math.h>

#define BB 32
#define TT 2048
#define DF 128
#define NN 16
#define DY 8
#define RECSZ 256
#define NTOK 32
#define NCHUNK 64                 // TT / NTOK
#define LOG2PI 1.8378770664093455f
#define LN2F 0.6931471805599453f

__device__ float g_rec[(size_t)BB * TT * RECSZ];   // zero-init; pad [192,256) never written
__device__ float g_llsum[BB];
__device__ int   g_flag[BB * NCHUNK];              // memset to 0 each launch

typedef unsigned long long ull;

__device__ __forceinline__ ull pk2(float a, float b) {
    ull r; asm("mov.b64 %0, {%1,%2};" : "=l"(r) : "f"(a), "f"(b)); return r;
}
__device__ __forceinline__ float sum2(ull v) {
    float a, b; asm("mov.b64 {%0,%1}, %2;" : "=f"(a), "=f"(b) : "l"(v)); return a + b;
}
__device__ __forceinline__ void unpk2(ull v, float& a, float& b) {
    asm("mov.b64 {%0,%1}, %2;" : "=f"(a), "=f"(b) : "l"(v));
}
__device__ __forceinline__ ull ffma2(ull a, ull b, ull c) {
    ull d; asm("fma.rn.f32x2 %0, %1, %2, %3;" : "=l"(d) : "l"(a), "l"(b), "l"(c)); return d;
}
__device__ __forceinline__ ull fmul2(ull a, ull b) {
    ull d; asm("mul.rn.f32x2 %0, %1, %2;" : "=l"(d) : "l"(a), "l"(b)); return d;
}
__device__ __forceinline__ ull fadd2(ull a, ull b) {
    ull d; asm("add.rn.f32x2 %0, %1, %2;" : "=l"(d) : "l"(a), "l"(b)); return d;
}
__device__ __forceinline__ float frcp(float x) {
    float r; asm("rcp.approx.f32 %0, %1;" : "=f"(r) : "f"(x)); return r;
}
__device__ __forceinline__ void cp16(float* s, const void* g) {
    unsigned a = (unsigned)__cvta_generic_to_shared(s);
    asm volatile("cp.async.cg.shared.global [%0], [%1], 16;" :: "r"(a), "l"(g));
}
__device__ __forceinline__ void cpcommit() { asm volatile("cp.async.commit_group;"); }
template<int N> __device__ __forceinline__ void cpwait() {
    asm volatile("cp.async.wait_group %0;" :: "n"(N));
}
#define BAR_SYNC(id)   asm volatile("bar.sync %0, 64;"   :: "r"(id) : "memory")
#define BAR_ARRIVE(id) asm volatile("bar.arrive %0, 64;" :: "r"(id) : "memory")

__device__ __forceinline__ float sp(float x) {
    return fmaxf(x, 0.f) + log1pf(expf(-fabsf(x)));
}
__device__ __forceinline__ float phik(float z, float k) {
    float kz = k * z;
    if (fabsf(kz) < 1e-4f) return 1.f + 0.5f * kz;
    return expm1f(kz) / kz;
}

__device__ __forceinline__ ull dot64(const float* __restrict__ row, const ull* xr2) {
    ull a0 = 0, a1 = 0, a2 = 0, a3 = 0;
#pragma unroll
    for (int k = 0; k < 8; k++) {
        ulonglong2 w0 = *(const ulonglong2*)(row + 8 * k);
        ulonglong2 w1 = *(const ulonglong2*)(row + 8 * k + 4);
        a0 = ffma2(w0.x, xr2[4 * k + 0], a0);
        a1 = ffma2(w0.y, xr2[4 * k + 1], a1);
        a2 = ffma2(w1.x, xr2[4 * k + 2], a2);
        a3 = ffma2(w1.y, xr2[4 * k + 3], a3);
    }
    return fadd2(fadd2(a0, a2), fadd2(a1, a3));
}

// producer dynamic smem layout (float offsets)
#define SM_SX    0
#define SM_SPART 4224
#define SM_SSML  12416
#define SM_W0    14080
#define SM_W1    30464
#define SM_TOT   46848
#define SM_BYTES (SM_TOT * 4)

__device__ __forceinline__ void stageW512(const float* src, float* dst, int tid) {
    const float4* s4 = (const float4*)src;
#pragma unroll
    for (int i = 0; i < 8; i++) {
        int idx = tid + i * 512;
        cp16(dst + idx * 4, s4 + idx);
    }
}

// ---------------------------------------------------------------------------
// Fused kernel: blocks 0..31 = scanners (2 warps), blocks 32.. = producers.
// ---------------------------------------------------------------------------
__global__ __launch_bounds__(512, 1) void fused_kernel(
    const float* __restrict__ x, const float* __restrict__ y,
    const float* __restrict__ a_raw,
    const float* __restrict__ Wg, const float* __restrict__ bg,
    const float* __restrict__ WB, const float* __restrict__ bB,
    const float* __restrict__ WC, const float* __restrict__ bC,
    const float* __restrict__ Ws, const float* __restrict__ bs,
    const float* __restrict__ WR, const float* __restrict__ bR,
    const float* __restrict__ p0, float* __restrict__ out)
{
    // ---- scanner static smem ----
    __shared__ __align__(16) float rec2[2][RECSZ];
    __shared__ __align__(16) float sP[320], sAug[8 * 36], sCPT[192];
    __shared__ __align__(16) float sKp[16 * 12], sInv[8 * 12];
    __shared__ __align__(16) float hpS[16];
    __shared__ __align__(16) float seS[8];
    __shared__ __align__(16) float sRed[4];

    if (blockIdx.x >= BB) {
        // ================= PRODUCER =================
        extern __shared__ float dsm[];
        float* sx    = dsm + SM_SX;
        float* spart = dsm + SM_SPART;
        float* ssml  = dsm + SM_SSML;
        float* sW0   = dsm + SM_W0;
        float* sW1   = dsm + SM_W1;

        const int tid = threadIdx.x;
        const int warp = tid >> 5, l = tid & 31;
        const int wf = warp & 7, half = warp >> 3;
        const int co = half * 64;
        const int p = blockIdx.x - BB;
        const int batch = p & 31, tchunk = p >> 5;         // time-major order
        const size_t base = (size_t)batch * TT + (size_t)tchunk * NTOK;

        stageW512(WB, sW0, tid);
        cpcommit();

        for (int k = tid; k < NTOK * DF; k += 512) {
            int tok = k >> 7, g = k & 127;
            sx[tok * 132 + g] = x[(base + tok) * DF + g];
        }
        __syncthreads();

        ull xr2[32];
#pragma unroll
        for (int k = 0; k < 16; k++) {
            ulonglong2 v = *(const ulonglong2*)(sx + l * 132 + co + 4 * k);
            xr2[2 * k] = v.x; xr2[2 * k + 1] = v.y;
        }

#pragma unroll
        for (int rr = 0; rr < 4; rr++) {
            int r = wf + 8 * rr;
            if (r < 25) {
                const float* Wrow; float bias;
                if (r == 0)      { Wrow = Wg;                 bias = bg[0]; }
                else if (r < 17) { Wrow = Ws + (r - 1) * DF;  bias = bs[r - 1]; }
                else             { Wrow = WR + (r - 17) * DF; bias = bR[r - 17]; }
                float v = sum2(dot64(Wrow + co, xr2));
                if (half == 0) v += bias;
                ssml[r * 66 + half * 33 + l] = v;
            }
        }

        for (int n = 0; n < NN; n++) {
            float* cur = (n & 1) ? sW1 : sW0;
            float* nxt = (n & 1) ? sW0 : sW1;
            __syncthreads();
            if (n < 15) { stageW512(WB + (size_t)(n + 1) * 16384, nxt, tid); cpcommit(); cpwait<1>(); }
            else        { cpwait<0>(); }
            __syncthreads();

            ull accn2 = 0;
            float bacc = 0.f;
#pragma unroll 4
            for (int fi = 0; fi < 16; fi++) {
                int f = wf + 8 * fi;
                ull rp = dot64(cur + f * 128 + co, xr2);
                float xf = sx[l * 132 + f];
                accn2 = ffma2(pk2(xf, xf), rp, accn2);
                if (half == 0) bacc += xf * bB[n * 128 + f];
            }
            spart[warp * 512 + n * 32 + l] = sum2(accn2) + bacc;
        }
        __syncthreads();

        stageW512(WC, sW0, tid);
        cpcommit();

        {
            int tok = tid & 31, n = tid >> 5;
            float hsum = 0.f;
#pragma unroll
            for (int w2 = 0; w2 < 16; w2++) hsum += spart[w2 * 512 + n * 32 + tok];
            float gate = ssml[tok] + ssml[33 + tok];
            float Delta = sp(gate) + 1e-6f;
            Delta = fminf(fmaxf(Delta, 1e-3f), 1.0f);
            float a = -(sp(a_raw[n]) + 1e-6f);
            float z = fminf(fmaxf(Delta * a, -20.f), 20.f);
            float ez  = expf(z);
            float gam = phik(z, 1.f);
            float rho = phik(z, 2.f);
            float sg = sp(ssml[(1 + n) * 66 + tok] + ssml[(1 + n) * 66 + 33 + tok]) + 1e-6f + 1e-3f;
            size_t rb = (base + tok) * RECSZ;
            g_rec[rb + n]      = ez;
            g_rec[rb + 16 + n] = gam * Delta * hsum;
            g_rec[rb + 32 + n] = sg * sg * rho * Delta;
            if (n < DY) {
                g_rec[rb + 176 + n] = sp(ssml[(17 + n) * 66 + tok] + ssml[(17 + n) * 66 + 33 + tok])
                                      + 1e-6f + 1e-4f;
                g_rec[rb + 184 + n] = y[(base + tok) * DY + n];
            }
        }
        cpwait<0>();
        __syncthreads();

#pragma unroll 4
        for (int jj = 0; jj < 16; jj++) {
            int j = wf * 16 + jj;
            spart[j * 64 + half * 32 + l] = sum2(dot64(sW0 + j * 128 + co, xr2));
        }
        __syncthreads();

        for (int idx = tid; idx < 1024; idx += 512) {
            int tok = idx & 31, j4 = (idx >> 5) * 4;
            float4 v;
            v.x = spart[(j4 + 0) * 64 + tok] + spart[(j4 + 0) * 64 + 32 + tok] + bC[j4 + 0];
            v.y = spart[(j4 + 1) * 64 + tok] + spart[(j4 + 1) * 64 + 32 + tok] + bC[j4 + 1];
            v.z = spart[(j4 + 2) * 64 + tok] + spart[(j4 + 2) * 64 + 32 + tok] + bC[j4 + 2];
            v.w = spart[(j4 + 3) * 64 + tok] + spart[(j4 + 3) * 64 + 32 + tok] + bC[j4 + 3];
            *(float4*)(&g_rec[(base + tok) * RECSZ + 48 + j4]) = v;
        }

        // publish chunk
        __threadfence();
        __syncthreads();
        if (tid == 0) atomicExch(&g_flag[batch * NCHUNK + tchunk], 1);
        return;
    }

    // ================= SCANNER (2 warps per batch) =================
    const int b = blockIdx.x, tid = threadIdx.x;
    if (tid >= 64) return;
    const int w = tid >> 5, l = tid & 31;
    const unsigned FULL = 0xffffffffu;

    float* om = out;
    float* ov = out + (size_t)BB * TT * DY;

    if (w == 0) {
        // ---------------- P-warp ----------------
        const int i2 = l >> 1, jb = (l & 1) * 8;
        const int d4 = l >> 2, j04 = (l & 3) * 4;

#pragma unroll
        for (int u = 0; u < 8; u++)
            sP[i2 * 20 + jb + u] = (i2 == jb + u) ? fabsf(p0[i2]) : 0.f;
        float mant = 1.f; int eacc = 0;          // lane 0

        // wait chunk 0, stage record 0 into buffer 0
        {
            volatile int* f = &g_flag[b * NCHUNK];
            while (*f == 0) __nanosleep(64);
        }
        __threadfence();
        const float* RB = g_rec + (size_t)b * TT * RECSZ;
        {
            float4 a0 = *(const float4*)(RB + l * 8);
            float4 a1 = *(const float4*)(RB + l * 8 + 4);
            *(float4*)(&rec2[0][l * 8])     = a0;
            *(float4*)(&rec2[0][l * 8 + 4]) = a1;
        }

        for (int t = 0; t < TT; t++) {
            BAR_SYNC(1);            // both warps: step start; rec/sP visible
            const float* rec = rec2[t & 1];
            float* rnx = rec2[(t + 1) & 1];

            // prefetch next record
            float4 pfa, pfb;
            {
                int tn = (t + 1 < TT) ? t + 1 : t;
                if (tn > t && (tn & 31) == 0) {
                    volatile int* f = &g_flag[b * NCHUNK + (tn >> 5)];
                    while (*f == 0) __nanosleep(64);
                    __threadfence();
                }
                const float* nx = RB + (size_t)tn * RECSZ;
                pfa = *(const float4*)(nx + l * 8);
                pfb = *(const float4*)(nx + l * 8 + 4);
            }

            // ---- CP (f32x2) ----
            {
                float4 ez0 = *(const float4*)&rec[0];
                float4 ez1 = *(const float4*)&rec[4];
                float4 ez2 = *(const float4*)&rec[8];
                float4 ez3 = *(const float4*)&rec[12];
                float ezl[16] = {ez0.x,ez0.y,ez0.z,ez0.w, ez1.x,ez1.y,ez1.z,ez1.w,
                                 ez2.x,ez2.y,ez2.z,ez2.w, ez3.x,ez3.y,ez3.z,ez3.w};
                const float* Crow = rec + 48 + d4 * 16;
                float4 ca = *(const float4*)(Crow);
                float4 cb = *(const float4*)(Crow + 4);
                float4 cc = *(const float4*)(Crow + 8);
                float4 cd = *(const float4*)(Crow + 12);
                float C[16] = {ca.x,ca.y,ca.z,ca.w, cb.x,cb.y,cb.z,cb.w,
                               cc.x,cc.y,cc.z,cc.w, cd.x,cd.y,cd.z,cd.w};
                ull accA = 0, accB = 0;
#pragma unroll
                for (int n = 0; n < 16; n++) {
                    float ch = C[n] * ezl[n];
                    ull ch2 = pk2(ch, ch);
                    ulonglong2 p = *(const ulonglong2*)&sP[n * 20 + j04];
                    accA = ffma2(ch2, p.x, accA);
                    accB = ffma2(ch2, p.y, accB);
                }
                ulonglong2 ezjp = *(const ulonglong2*)&rec[j04];
                ulonglong2 qvp  = *(const ulonglong2*)&rec[32 + j04];
                ulonglong2 cjp  = *(const ulonglong2*)(Crow + j04);
                ull cp01 = ffma2(cjp.x, qvp.x, fmul2(ezjp.x, accA));
                ull cp23 = ffma2(cjp.y, qvp.y, fmul2(ezjp.y, accB));
                ulonglong2 cps; cps.x = cp01; cps.y = cp23;
                *(ulonglong2*)&sAug[d4 * 36 + 8 + j04] = cps;
                float c0f, c1f, c2f, c3f;
                unpk2(cp01, c0f, c1f); unpk2(cp23, c2f, c3f);
                sCPT[(j04 + 0) * 12 + d4] = c0f;
                sCPT[(j04 + 1) * 12 + d4] = c1f;
                sCPT[(j04 + 2) * 12 + d4] = c2f;
                sCPT[(j04 + 3) * 12 + d4] = c3f;
            }
            __syncwarp(FULL);

            // ---- S (2 per lane, diag -> ov direct) ----
            {
                int d = d4, q0 = (l & 3) * 2;
                ulonglong2 g0 = *(const ulonglong2*)&sAug[d * 36 + 8];
                ulonglong2 g1 = *(const ulonglong2*)&sAug[d * 36 + 12];
                ulonglong2 g2 = *(const ulonglong2*)&sAug[d * 36 + 16];
                ulonglong2 g3 = *(const ulonglong2*)&sAug[d * 36 + 20];
#pragma unroll
                for (int qq = 0; qq < 2; qq++) {
                    int q = q0 + qq;
                    ulonglong2 c0 = *(const ulonglong2*)&rec[48 + q * 16];
                    ulonglong2 c1 = *(const ulonglong2*)&rec[48 + q * 16 + 4];
                    ulonglong2 c2 = *(const ulonglong2*)&rec[48 + q * 16 + 8];
                    ulonglong2 c3 = *(const ulonglong2*)&rec[48 + q * 16 + 12];
                    ull x0 = ffma2(g0.x, c0.x, ffma2(g0.y, c0.y, 0));
                    ull x1 = ffma2(g1.x, c1.x, ffma2(g1.y, c1.y, 0));
                    ull x2 = ffma2(g2.x, c2.x, ffma2(g2.y, c2.y, 0));
                    ull x3 = ffma2(g3.x, c3.x, ffma2(g3.y, c3.y, 0));
                    float s = sum2(fadd2(fadd2(x0, x1), fadd2(x2, x3)));
                    if (d == q) {
                        s += rec[176 + d];
                        ov[((size_t)b * TT + t) * DY + d] = s;
                    }
                    sAug[d * 36 + q] = s;
                }
            }
            __syncwarp(FULL);

            // ---- GJ on [S | CP | I]: lane = column ----
            float r[8];
            if (l < 24) {
#pragma unroll
                for (int d = 0; d < 8; d++) r[d] = sAug[d * 36 + l];
            } else {
                int q = l - 24;
#pragma unroll
                for (int d = 0; d < 8; d++) r[d] = (d == q) ? 1.f : 0.f;
            }
            float pprod = 1.f;
#pragma unroll
            for (int k = 0; k < 4; k++) {
                const int p0i = 2 * k, p1i = 2 * k + 1;
                float r0 = r[p0i], r1 = r[p1i];
                float pa = __shfl_sync(FULL, r0, p0i);
                float pc = __shfl_sync(FULL, r1, p0i);
                float pb = __shfl_sync(FULL, r0, p1i);
                float pd = __shfl_sync(FULL, r1, p1i);
                float det = pa * pd - pb * pc;
                pprod *= det;
                float rdet = frcp(det);
                float n0 = rdet * (pd * r0 - pb * r1);
                float n1 = rdet * (pa * r1 - pc * r0);
#pragma unroll
                for (int i = 0; i < 8; i++) {
                    if (i == p0i || i == p1i) continue;
                    float m0 = __shfl_sync(FULL, r[i], p0i);
                    float m1 = __shfl_sync(FULL, r[i], p1i);
                    r[i] -= m0 * n0 + m1 * n1;
                }
                r[p0i] = n0; r[p1i] = n1;
            }
            // publish K'^T (lanes 8..23) and S^-1 (lanes 24..31)
            if (l >= 8 && l < 24) {
                int n = l - 8;
                *(float4*)&sKp[n * 12]     = make_float4(r[0], r[1], r[2], r[3]);
                *(float4*)&sKp[n * 12 + 4] = make_float4(r[4], r[5], r[6], r[7]);
            } else if (l >= 24) {
                int q = l - 24;
                *(float4*)&sInv[q * 12]     = make_float4(r[0], r[1], r[2], r[3]);
                *(float4*)&sInv[q * 12 + 4] = make_float4(r[4], r[5], r[6], r[7]);
            }
            BAR_ARRIVE(2);

            if (l == 0) {
                int e1i; float m1f = frexpf(pprod, &e1i);
                int e2i; mant = frexpf(mant * m1f, &e2i);
                eacc += e1i + e2i;
            }

            // ---- P_new: K' column i2 via shfl from lane 8+i2 ----
            {
                float m0 = __shfl_sync(FULL, r[0], 8 + i2);
                float m1 = __shfl_sync(FULL, r[1], 8 + i2);
                float m2 = __shfl_sync(FULL, r[2], 8 + i2);
                float m3 = __shfl_sync(FULL, r[3], 8 + i2);
                float m4 = __shfl_sync(FULL, r[4], 8 + i2);
                float m5 = __shfl_sync(FULL, r[5], 8 + i2);
                float m6 = __shfl_sync(FULL, r[6], 8 + i2);
                float m7 = __shfl_sync(FULL, r[7], 8 + i2);
                ull K0 = pk2(m0, m1), K1 = pk2(m2, m3);
                ull K2 = pk2(m4, m5), K3 = pk2(m6, m7);
                float ezi = rec[i2];
                float qi  = rec[32 + i2];
                float4 ej0 = *(const float4*)&rec[jb];
                float4 ej1 = *(const float4*)&rec[jb + 4];
                float ej[8] = {ej0.x,ej0.y,ej0.z,ej0.w, ej1.x,ej1.y,ej1.z,ej1.w};
                float4 pav = *(const float4*)&sP[i2 * 20 + jb];
                float4 pbv = *(const float4*)&sP[i2 * 20 + jb + 4];
                float pv[8] = {pav.x,pav.y,pav.z,pav.w, pbv.x,pbv.y,pbv.z,pbv.w};
                float o[8];
#pragma unroll
                for (int u = 0; u < 8; u++) {
                    int j = jb + u;
                    ulonglong2 c0 = *(const ulonglong2*)&sCPT[j * 12];
                    ulonglong2 c1 = *(const ulonglong2*)&sCPT[j * 12 + 4];
                    ull acc = ffma2(K0, c0.x, ffma2(K1, c0.y,
                              ffma2(K2, c1.x, ffma2(K3, c1.y, 0))));
                    o[u] = ezi * ej[u] * pv[u] - sum2(acc) + ((i2 == j) ? qi : 0.f);
                }
                *(float4*)&sP[i2 * 20 + jb]     = make_float4(o[0], o[1], o[2], o[3]);
                *(float4*)&sP[i2 * 20 + jb + 4] = make_float4(o[4], o[5], o[6], o[7]);
            }
            // stage next record
            *(float4*)(&rnx[l * 8])     = pfa;
            *(float4*)(&rnx[l * 8 + 4]) = pfb;
        }
        if (l == 0) { sRed[0] = mant; ((int*)sRed)[1] = eacc; }
        BAR_SYNC(1);
        if (l == 0) {
            float logdet_sum = logf(sRed[0]) + (float)(((int*)sRed)[1]) * LN2F;
            g_llsum[b] = -0.5f * (logdet_sum + sRed[2] + (float)TT * (float)DY * LOG2PI);
        }
    } else {
        // ---------------- h-warp ----------------
        float hh_reg = 0.f, hp_reg = 0.f;        // lanes 0..15
        float q_s = 0.f, q_c = 0.f;              // lane 16

        for (int t = 0; t < TT; t++) {
            BAR_SYNC(1);
            const float* rec = rec2[t & 1];

            // hp (lanes 0..15)
            if (l < 16) {
                hp_reg = rec[l] * hh_reg + rec[16 + l];
                hpS[l] = hp_reg;
            }
            __syncwarp(FULL);

            // y_pred (all lanes, dd = l&7), e
            int dd = l & 7;
            {
                const float* Cd = rec + 48 + dd * 16;
                ulonglong2 cd0 = *(const ulonglong2*)(Cd);
                ulonglong2 cd1 = *(const ulonglong2*)(Cd + 4);
                ulonglong2 cd2 = *(const ulonglong2*)(Cd + 8);
                ulonglong2 cd3 = *(const ulonglong2*)(Cd + 12);
                ulonglong2 h0 = *(const ulonglong2*)&hpS[0];
                ulonglong2 h1 = *(const ulonglong2*)&hpS[4];
                ulonglong2 h2 = *(const ulonglong2*)&hpS[8];
                ulonglong2 h3 = *(const ulonglong2*)&hpS[12];
                ull ya = ffma2(cd0.x, h0.x, ffma2(cd0.y, h0.y, 0));
                ull yb = ffma2(cd1.x, h1.x, ffma2(cd1.y, h1.y, 0));
                ull yc = ffma2(cd2.x, h2.x, ffma2(cd2.y, h2.y, 0));
                ull yd = ffma2(cd3.x, h3.x, ffma2(cd3.y, h3.y, 0));
                float yp = sum2(fadd2(fadd2(ya, yb), fadd2(yc, yd)));
                float ee = rec[184 + dd] - yp;
                if (l >= 24) {
                    om[((size_t)b * TT + t) * DY + dd] = yp;
                    seS[dd] = ee;
                }
            }
            __syncwarp(FULL);

            BAR_SYNC(2);            // K'^T + S^-1 published by P-warp

            if (l < 16) {
                ulonglong2 k0 = *(const ulonglong2*)&sKp[l * 12];
                ulonglong2 k1 = *(const ulonglong2*)&sKp[l * 12 + 4];
                ulonglong2 e0 = *(const ulonglong2*)&seS[0];
                ulonglong2 e1 = *(const ulonglong2*)&seS[4];
                ull acc = ffma2(k0.x, e0.x, ffma2(k0.y, e0.y,
                          ffma2(k1.x, e1.x, ffma2(k1.y, e1.y, 0))));
                hh_reg = hp_reg + sum2(acc);
            } else if (l < 24) {
                const unsigned GMASK = 0x00ff0000u;      // lanes 16..23 only
                int d = l - 16;
                float vd = 0.f;
#pragma unroll
                for (int q = 0; q < 8; q++) vd += sInv[q * 12 + d] * seS[q];
                float pv = seS[d] * vd;
                pv += __shfl_down_sync(GMASK, pv, 4);
                pv += __shfl_down_sync(GMASK, pv, 2);
                pv += __shfl_down_sync(GMASK, pv, 1);
                if (d == 0) {
                    float yk = pv - q_c, tk = q_s + yk;
                    q_c = (tk - q_s) - yk; q_s = tk;
                }
            }
        }
        if (l == 16) sRed[2] = q_s;
        BAR_SYNC(1);
    }
}

__global__ void phase3_kernel(float* __restrict__ out) {
    float v = g_llsum[threadIdx.x];
#pragma unroll
    for (int o = 16; o > 0; o >>= 1) v += __shfl_down_sync(0xffffffffu, v, o);
    if (threadIdx.x == 0) {
        size_t off = (size_t)2 * BB * TT * DY;
        out[off]     = -v / (float)BB;
        out[off + 1] =  v / (float)(BB * TT);
    }
}

extern "C" void kernel_launch(void* const* d_in, const int* in_sizes, int n_in,
                              void* d_out, int out_size) {
    const float* x_feat = (const float*)d_in[0];
    const float* y      = (const float*)d_in[1];
    const float* a_raw  = (const float*)d_in[2];
    const float* W_gate = (const float*)d_in[3];
    const float* b_gate = (const float*)d_in[4];
    const float* W_B    = (const float*)d_in[5];
    const float* b_B    = (const float*)d_in[6];
    const float* W_C    = (const float*)d_in[7];
    const float* b_C    = (const float*)d_in[8];
    const float* W_sig  = (const float*)d_in[9];
    const float* b_sig  = (const float*)d_in[10];
    const float* W_R    = (const float*)d_in[11];
    const float* b_R    = (const float*)d_in[12];
    const float* p0     = (const float*)d_in[13];
    float* out = (float*)d_out;

    void* flag_ptr = nullptr;
    cudaGetSymbolAddress(&flag_ptr, g_flag);
    cudaMemsetAsync(flag_ptr, 0, BB * NCHUNK * sizeof(int), 0);

    cudaFuncSetAttribute(fused_kernel,
                         cudaFuncAttributeMaxDynamicSharedMemorySize, SM_BYTES);
    fused_kernel<<<BB + (BB * TT) / NTOK, 512, SM_BYTES>>>(
        x_feat, y, a_raw, W_gate, b_gate, W_B, b_B, W_C, b_C,
        W_sig, b_sig, W_R, b_R, p0, out);
    phase3_kernel<<<1, 32>>>(out);
}